// round 2
// baseline (speedup 1.0000x reference)
#include <cuda_runtime.h>
#include <cstdint>
#include <cstddef>

// ---------------- problem constants ----------------
#define T_   256
#define B_   64
#define I_   512
#define H_   1024
#define O_   512
#define K_   8
#define G3   (3*H_)          // 3072
#define BH   (B_*H_)         // 65536
#define TBO  (T_*B_*O_)      // 8388608  (outs elements)

// recurrence kernel config
#define NCTA 128             // persistent CTAs (1 per SM, all resident)
#define HSL  8               // H columns owned per CTA (128*8 = 1024)
#define GC   24              // gate columns per CTA (3 gates * HSL)
#define CHK  128             // k-chunk staged in smem
#define HSTR 66              // padded row stride for transposed h chunk

// smem carve (floats): Whs | hs | red | wS
#define SM_WHS   (H_*GC)         // 24576
#define SM_HS    (CHK*HSTR)      // 8448
#define SM_RED   (4*1536)        // 6144
#define SM_WS    64
#define SM_FLOATS (SM_WHS + SM_HS + SM_RED + SM_WS)   // 39232
#define SMEM_BYTES (SM_FLOATS*4)                      // 156928 B

// ---------------- device scratch (static: allocation-free) ----------------
__device__ float    g_GX[(size_t)T_*B_*G3];          // (T,B,3H) precomputed x@Wx+b  (~201 MB)
__device__ float    g_Hbuf[(size_t)(K_+T_)*BH];      // slots: [0,K) initial, [K, K+T) new states (~66 MB)
__device__ float    g_w[K_*H_];                      // fractional weights, index 0 = oldest
__device__ unsigned g_bar;                           // monotonic grid barrier counter

__device__ __forceinline__ float sigf(float x) { return 1.0f/(1.0f + __expf(-x)); }

// ---------------- init: barrier reset + GL weights + initial hidden copy ----------------
__global__ void init_kernel(const float* __restrict__ hid, const float* __restrict__ mp)
{
    int idx = blockIdx.x*blockDim.x + threadIdx.x;
    if (idx == 0) g_bar = 0u;
    if (idx < H_) {
        float a = 0.5f / (1.0f + expf(-mp[idx]));   // alpha
        float c = 1.0f;
        #pragma unroll
        for (int i = 0; i < K_; i++) {
            c *= ((float)i + a) / ((float)i + 1.0f);
            g_w[(K_-1-i)*H_ + idx] = c;             // w[K-1-i] = cumprod, index 0 = oldest
        }
    }
    const int n = K_*BH;
    for (int i = idx; i < n; i += gridDim.x*blockDim.x)
        g_Hbuf[i] = hid[i];
}

// ---------------- classic 128x128x8 SGEMM with bias (C = A@B + bias) ----------------
// A: MxK row-major, B: KxN row-major, bias: N, C: MxN row-major.
// Requires M%128==0, N%128==0, K%8==0 (true for all uses here).
__global__ __launch_bounds__(256) void sgemm128(
    const float* __restrict__ A, const float* __restrict__ Bm,
    const float* __restrict__ bias, float* __restrict__ C,
    int M, int N, int Kd)
{
    __shared__ float As[8][128];
    __shared__ float Bs[8][128];
    const int tid  = threadIdx.x;
    const int bx   = blockIdx.x, by = blockIdx.y;
    const int trow = tid >> 4;          // 0..15
    const int tcol = tid & 15;          // 0..15

    float acc[8][8];
    #pragma unroll
    for (int i = 0; i < 8; i++)
        #pragma unroll
        for (int j = 0; j < 8; j++) acc[i][j] = 0.0f;

    const float* Ab = A  + (size_t)by*128*Kd;
    const float* Bb = Bm + (size_t)bx*128;
    const int arow = tid >> 1, acol = (tid & 1) << 2;   // 128 rows x 8 cols (two float4/row)
    const int brow = tid >> 5, bcol = (tid & 31) << 2;  // 8 rows x 128 cols

    for (int k0 = 0; k0 < Kd; k0 += 8) {
        float4 av = *(const float4*)(Ab + (size_t)arow*Kd + k0 + acol);
        As[acol+0][arow] = av.x; As[acol+1][arow] = av.y;
        As[acol+2][arow] = av.z; As[acol+3][arow] = av.w;
        *(float4*)&Bs[brow][bcol] = *(const float4*)(Bb + (size_t)(k0 + brow)*N + bcol);
        __syncthreads();
        #pragma unroll
        for (int k = 0; k < 8; k++) {
            float4 a0 = *(float4*)&As[k][trow*8];
            float4 a1 = *(float4*)&As[k][trow*8 + 4];
            float4 b0 = *(float4*)&Bs[k][tcol*8];
            float4 b1 = *(float4*)&Bs[k][tcol*8 + 4];
            float ra[8] = {a0.x,a0.y,a0.z,a0.w,a1.x,a1.y,a1.z,a1.w};
            float rb[8] = {b0.x,b0.y,b0.z,b0.w,b1.x,b1.y,b1.z,b1.w};
            #pragma unroll
            for (int i = 0; i < 8; i++)
                #pragma unroll
                for (int j = 0; j < 8; j++)
                    acc[i][j] = fmaf(ra[i], rb[j], acc[i][j]);
        }
        __syncthreads();
    }

    #pragma unroll
    for (int i = 0; i < 8; i++) {
        int row = by*128 + trow*8 + i;
        float*       Cr = C    + (size_t)row*N + bx*128 + tcol*8;
        const float* br = bias + (size_t)bx*128 + tcol*8;
        #pragma unroll
        for (int j = 0; j < 8; j += 4) {
            float4 v;
            v.x = acc[i][j+0] + br[j+0];
            v.y = acc[i][j+1] + br[j+1];
            v.z = acc[i][j+2] + br[j+2];
            v.w = acc[i][j+3] + br[j+3];
            *(float4*)(Cr + j) = v;
        }
    }
}

// ---------------- persistent recurrence kernel ----------------
// 128 CTAs, each owns 8 H-columns. Wh slice (24 cols x 1024) resident in smem.
// Per step: gh-slice GEMM (k-split x4), gates + fractional memory + h_new, grid barrier.
extern __shared__ float smemBuf[];

__global__ __launch_bounds__(256, 1) void recur_kernel(const float* __restrict__ Wh)
{
    float* Whs = smemBuf;            // [1024][24]  resident Wh columns
    float* hs  = Whs + SM_WHS;       // [CHK][HSTR] transposed h chunk
    float* red = hs  + SM_HS;        // [4][24][64] k-split partials
    float* wS  = red + SM_RED;       // [K][8]      fractional weights for this slice
    const int tid = threadIdx.x;
    const int c0  = blockIdx.x * HSL;

    // one-time: stage Wh columns {c0+j, H+c0+j, 2H+c0+j}
    for (int idx = tid; idx < H_*GC; idx += 256) {
        int k = idx / GC, j = idx - k*GC;
        int col = (j >> 3)*H_ + c0 + (j & 7);
        Whs[idx] = Wh[(size_t)k*G3 + col];
    }
    if (tid < K_*HSL) wS[tid] = g_w[(tid >> 3)*H_ + c0 + (tid & 7)];
    __syncthreads();

    const int ks  = tid >> 6;        // k-split 0..3
    const int jg  = (tid >> 4) & 3;  // j-group (6 cols each)
    const int bpg = tid & 15;        // batch group (4 b's each)

    for (int t = 0; t < T_; t++) {
        const float* hp = g_Hbuf + (size_t)(K_ + t - 1)*BH;   // most recent hidden
        float acc[6][4];
        #pragma unroll
        for (int a = 0; a < 6; a++)
            #pragma unroll
            for (int bb = 0; bb < 4; bb++) acc[a][bb] = 0.0f;

        for (int k0 = 0; k0 < H_; k0 += CHK) {
            // stage transposed h chunk: hs[k][b]
            for (int idx = tid; idx < B_*(CHK/4); idx += 256) {
                int b  = idx >> 5;
                int k4 = (idx & 31) << 2;
                float4 v = *(const float4*)(hp + (size_t)b*H_ + k0 + k4);
                hs[(k4+0)*HSTR + b] = v.x;
                hs[(k4+1)*HSTR + b] = v.y;
                hs[(k4+2)*HSTR + b] = v.z;
                hs[(k4+3)*HSTR + b] = v.w;
            }
            __syncthreads();
            const float* hcol = hs  + 4*bpg;
            const float* wcol = Whs + jg*6;
            #pragma unroll 4
            for (int kl = 0; kl < CHK/4; kl++) {
                int k = ks*(CHK/4) + kl;                 // chunk-local k (0..127)
                const float* hr = hcol + (size_t)k*HSTR;
                float h0 = hr[0], h1 = hr[1], h2 = hr[2], h3 = hr[3];
                const float* wr = wcol + (size_t)(k0 + k)*GC;   // FIX: global k into Whs
                #pragma unroll
                for (int j = 0; j < 6; j++) {
                    float w = wr[j];
                    acc[j][0] = fmaf(w, h0, acc[j][0]);
                    acc[j][1] = fmaf(w, h1, acc[j][1]);
                    acc[j][2] = fmaf(w, h2, acc[j][2]);
                    acc[j][3] = fmaf(w, h3, acc[j][3]);
                }
            }
            __syncthreads();
        }

        // k-split partials -> smem
        #pragma unroll
        for (int j = 0; j < 6; j++)
            #pragma unroll
            for (int bi = 0; bi < 4; bi++)
                red[ks*1536 + (jg*6 + j)*64 + bpg*4 + bi] = acc[j][bi];
        __syncthreads();

        // epilogue: gates + fractional memory + h_new for (64 b x 8 h)
        for (int o = tid; o < B_*HSL; o += 256) {
            int b = o >> 3, hc = o & 7;
            float gz = 0.f, gr = 0.f, gn = 0.f;
            #pragma unroll
            for (int s = 0; s < 4; s++) {
                gz += red[s*1536 + (hc     )*64 + b];
                gr += red[s*1536 + (8  + hc)*64 + b];
                gn += red[s*1536 + (16 + hc)*64 + b];
            }
            int hg = c0 + hc;
            const float* gx = g_GX + ((size_t)t*B_ + b)*G3;
            float z = sigf(gx[hg]        + gz);
            float r = sigf(gx[H_  + hg]  + gr);
            float n = tanhf(gx[2*H_ + hg] + r*gn);
            float mem = 0.f;
            #pragma unroll
            for (int kk = 0; kk < K_; kk++)
                mem = fmaf(wS[kk*8 + hc],
                           g_Hbuf[(size_t)(t + kk)*BH + (size_t)b*H_ + hg], mem);
            g_Hbuf[(size_t)(K_ + t)*BH + (size_t)b*H_ + hg] = (1.0f - z)*n + z*mem;
        }

        // grid barrier (monotonic counter, reset each launch by init_kernel)
        __threadfence();
        __syncthreads();
        if (tid == 0) {
            atomicAdd(&g_bar, 1u);
            unsigned target = (unsigned)NCTA * (unsigned)(t + 1);
            while (*(volatile unsigned*)&g_bar < target) { __nanosleep(64); }
        }
        __syncthreads();
    }
}

// ---------------- tail: write H_fin (last K states, oldest first) ----------------
__global__ void tail_kernel(float* __restrict__ outTail)
{
    const int n = K_*BH;
    for (int i = blockIdx.x*blockDim.x + threadIdx.x; i < n; i += gridDim.x*blockDim.x)
        outTail[i] = g_Hbuf[(size_t)T_*BH + i];
}

// ---------------- launch ----------------
extern "C" void kernel_launch(void* const* d_in, const int* in_sizes, int n_in,
                              void* d_out, int out_size)
{
    const float* inputs = (const float*)d_in[0];  // (T,B,I)
    const float* hidden = (const float*)d_in[1];  // (K,B,H)
    const float* Wx     = (const float*)d_in[2];  // (I,3H)
    const float* Wh     = (const float*)d_in[3];  // (H,3H)
    const float* b      = (const float*)d_in[4];  // (3H,)
    const float* Wo     = (const float*)d_in[5];  // (H,O)
    const float* bo     = (const float*)d_in[6];  // (O,)
    const float* mp     = (const float*)d_in[7];  // (1,H)
    float* out = (float*)d_out;

    void* gxp = nullptr; cudaGetSymbolAddress(&gxp, g_GX);
    void* hbp = nullptr; cudaGetSymbolAddress(&hbp, g_Hbuf);

    cudaFuncSetAttribute(recur_kernel, cudaFuncAttributeMaxDynamicSharedMemorySize, SMEM_BYTES);

    // 1. barrier reset + GL weights + initial hidden copy
    init_kernel<<<256, 256>>>(hidden, mp);

    // 2. GX = X @ Wx + b   (M=16384, N=3072, K=512)
    sgemm128<<<dim3(G3/128, (T_*B_)/128), 256>>>(inputs, Wx, b, (float*)gxp,
                                                 T_*B_, G3, I_);

    // 3. sequential recurrence (persistent, 256 steps)
    recur_kernel<<<NCTA, 256, SMEM_BYTES>>>(Wh);

    // 4. outs = H_all @ Wo + bo   (M=16384, N=512, K=1024)
    sgemm128<<<dim3(O_/128, (T_*B_)/128), 256>>>((const float*)hbp + (size_t)K_*BH,
                                                 Wo, bo, out, T_*B_, O_, H_);

    // 5. H_fin tail
    if (out_size >= TBO + K_*BH)
        tail_kernel<<<256, 256>>>(out + TBO);
}

// round 3
// speedup vs baseline: 1.0039x; 1.0039x over previous
#include <cuda_runtime.h>
#include <cstdint>
#include <cstddef>

// ---------------- problem constants ----------------
#define T_   256
#define B_   64
#define I_   512
#define H_   1024
#define O_   512
#define K_   8
#define G3   (3*H_)          // 3072
#define BH   (B_*H_)         // 65536
#define TBO  (T_*B_*O_)      // 8388608  (outs elements)

// recurrence kernel config
#define NCTA 128             // persistent CTAs (1 per SM, all resident)
#define HSL  8               // H columns owned per CTA (128*8 = 1024)
#define GC   24              // gate columns per CTA (3 gates * HSL)
#define CHK  128             // k-chunk staged in smem
#define HSTR 66              // padded row stride for transposed h chunk

// smem carve (floats): Whs | hs | red | wS
#define SM_WHS   (H_*GC)         // 24576
#define SM_HS    (CHK*HSTR)      // 8448
#define SM_RED   (4*1536)        // 6144
#define SM_WS    64
#define SM_FLOATS (SM_WHS + SM_HS + SM_RED + SM_WS)   // 39232
#define SMEM_BYTES (SM_FLOATS*4)                      // 156928 B

// ---------------- device scratch (static: allocation-free) ----------------
__device__ float    g_GX[(size_t)T_*B_*G3];          // (T,B,3H) precomputed x@Wx+b  (~201 MB)
__device__ float    g_Hbuf[(size_t)(K_+T_)*BH];      // slots: [0,K) initial, [K, K+T) new states (~66 MB)
__device__ float    g_w[K_*H_];                      // fractional weights, index 0 = oldest
__device__ unsigned g_bar;                           // monotonic grid barrier counter

__device__ __forceinline__ float sigf(float x) { return 1.0f/(1.0f + __expf(-x)); }

// ---------------- init: barrier reset + GL weights + initial hidden copy ----------------
__global__ void init_kernel(const float* __restrict__ hid, const float* __restrict__ mp)
{
    int idx = blockIdx.x*blockDim.x + threadIdx.x;
    if (idx == 0) g_bar = 0u;
    if (idx < H_) {
        float a = 0.5f / (1.0f + expf(-mp[idx]));   // alpha
        float c = 1.0f;
        #pragma unroll
        for (int i = 0; i < K_; i++) {
            c *= ((float)i + a) / ((float)i + 1.0f);
            g_w[(K_-1-i)*H_ + idx] = c;             // w[K-1-i] = cumprod, index 0 = oldest
        }
    }
    const int n = K_*BH;
    for (int i = idx; i < n; i += gridDim.x*blockDim.x)
        g_Hbuf[i] = hid[i];
}

// ---------------- classic 128x128x8 SGEMM with bias (C = A@B + bias) ----------------
// A: MxK row-major, B: KxN row-major, bias: N, C: MxN row-major.
// Requires M%128==0, N%128==0, K%8==0 (true for all uses here).
__global__ __launch_bounds__(256) void sgemm128(
    const float* __restrict__ A, const float* __restrict__ Bm,
    const float* __restrict__ bias, float* __restrict__ C,
    int M, int N, int Kd)
{
    __shared__ float As[8][128];
    __shared__ float Bs[8][128];
    const int tid  = threadIdx.x;
    const int bx   = blockIdx.x, by = blockIdx.y;
    const int trow = tid >> 4;          // 0..15
    const int tcol = tid & 15;          // 0..15

    float acc[8][8];
    #pragma unroll
    for (int i = 0; i < 8; i++)
        #pragma unroll
        for (int j = 0; j < 8; j++) acc[i][j] = 0.0f;

    const float* Ab = A  + (size_t)by*128*Kd;
    const float* Bb = Bm + (size_t)bx*128;
    const int arow = tid >> 1, acol = (tid & 1) << 2;   // 128 rows x 8 cols (two float4/row)
    const int brow = tid >> 5, bcol = (tid & 31) << 2;  // 8 rows x 128 cols

    for (int k0 = 0; k0 < Kd; k0 += 8) {
        float4 av = *(const float4*)(Ab + (size_t)arow*Kd + k0 + acol);
        As[acol+0][arow] = av.x; As[acol+1][arow] = av.y;
        As[acol+2][arow] = av.z; As[acol+3][arow] = av.w;
        *(float4*)&Bs[brow][bcol] = *(const float4*)(Bb + (size_t)(k0 + brow)*N + bcol);
        __syncthreads();
        #pragma unroll
        for (int k = 0; k < 8; k++) {
            float4 a0 = *(float4*)&As[k][trow*8];
            float4 a1 = *(float4*)&As[k][trow*8 + 4];
            float4 b0 = *(float4*)&Bs[k][tcol*8];
            float4 b1 = *(float4*)&Bs[k][tcol*8 + 4];
            float ra[8] = {a0.x,a0.y,a0.z,a0.w,a1.x,a1.y,a1.z,a1.w};
            float rb[8] = {b0.x,b0.y,b0.z,b0.w,b1.x,b1.y,b1.z,b1.w};
            #pragma unroll
            for (int i = 0; i < 8; i++)
                #pragma unroll
                for (int j = 0; j < 8; j++)
                    acc[i][j] = fmaf(ra[i], rb[j], acc[i][j]);
        }
        __syncthreads();
    }

    #pragma unroll
    for (int i = 0; i < 8; i++) {
        int row = by*128 + trow*8 + i;
        float*       Cr = C    + (size_t)row*N + bx*128 + tcol*8;
        const float* br = bias + (size_t)bx*128 + tcol*8;
        #pragma unroll
        for (int j = 0; j < 8; j += 4) {
            float4 v;
            v.x = acc[i][j+0] + br[j+0];
            v.y = acc[i][j+1] + br[j+1];
            v.z = acc[i][j+2] + br[j+2];
            v.w = acc[i][j+3] + br[j+3];
            *(float4*)(Cr + j) = v;
        }
    }
}

// ---------------- persistent recurrence kernel ----------------
// 128 CTAs, each owns 8 H-columns. Wh slice (24 cols x 1024) resident in smem.
// Per step: gh-slice GEMM (k-split x4), gates + fractional memory + h_new, grid barrier.
extern __shared__ float smemBuf[];

__global__ __launch_bounds__(256, 1) void recur_kernel(const float* __restrict__ Wh)
{
    float* Whs = smemBuf;            // [1024][24]  resident Wh columns
    float* hs  = Whs + SM_WHS;       // [CHK][HSTR] transposed h chunk
    float* red = hs  + SM_HS;        // [4][24][64] k-split partials
    float* wS  = red + SM_RED;       // [K][8]      fractional weights for this slice
    const int tid = threadIdx.x;
    const int c0  = blockIdx.x * HSL;

    // one-time: stage Wh columns {c0+j, H+c0+j, 2H+c0+j}
    for (int idx = tid; idx < H_*GC; idx += 256) {
        int k = idx / GC, j = idx - k*GC;
        int col = (j >> 3)*H_ + c0 + (j & 7);
        Whs[idx] = Wh[(size_t)k*G3 + col];
    }
    if (tid < K_*HSL) wS[tid] = g_w[(tid >> 3)*H_ + c0 + (tid & 7)];
    __syncthreads();

    const int ks  = tid >> 6;        // k-split 0..3
    const int jg  = (tid >> 4) & 3;  // j-group (6 cols each)
    const int bpg = tid & 15;        // batch group (4 b's each)

    for (int t = 0; t < T_; t++) {
        const float* hp = g_Hbuf + (size_t)(K_ + t - 1)*BH;   // most recent hidden
        float acc[6][4];
        #pragma unroll
        for (int a = 0; a < 6; a++)
            #pragma unroll
            for (int bb = 0; bb < 4; bb++) acc[a][bb] = 0.0f;

        for (int k0 = 0; k0 < H_; k0 += CHK) {
            // stage transposed h chunk: hs[k][b]
            for (int idx = tid; idx < B_*(CHK/4); idx += 256) {
                int b  = idx >> 5;
                int k4 = (idx & 31) << 2;
                float4 v = *(const float4*)(hp + (size_t)b*H_ + k0 + k4);
                hs[(k4+0)*HSTR + b] = v.x;
                hs[(k4+1)*HSTR + b] = v.y;
                hs[(k4+2)*HSTR + b] = v.z;
                hs[(k4+3)*HSTR + b] = v.w;
            }
            __syncthreads();
            const float* hcol = hs  + 4*bpg;
            const float* wcol = Whs + jg*6;
            #pragma unroll 4
            for (int kl = 0; kl < CHK/4; kl++) {
                int k = ks*(CHK/4) + kl;                 // chunk-local k (0..127)
                const float* hr = hcol + (size_t)k*HSTR;
                float h0 = hr[0], h1 = hr[1], h2 = hr[2], h3 = hr[3];
                const float* wr = wcol + (size_t)(k0 + k)*GC;   // FIX: global k into Whs
                #pragma unroll
                for (int j = 0; j < 6; j++) {
                    float w = wr[j];
                    acc[j][0] = fmaf(w, h0, acc[j][0]);
                    acc[j][1] = fmaf(w, h1, acc[j][1]);
                    acc[j][2] = fmaf(w, h2, acc[j][2]);
                    acc[j][3] = fmaf(w, h3, acc[j][3]);
                }
            }
            __syncthreads();
        }

        // k-split partials -> smem
        #pragma unroll
        for (int j = 0; j < 6; j++)
            #pragma unroll
            for (int bi = 0; bi < 4; bi++)
                red[ks*1536 + (jg*6 + j)*64 + bpg*4 + bi] = acc[j][bi];
        __syncthreads();

        // epilogue: gates + fractional memory + h_new for (64 b x 8 h)
        for (int o = tid; o < B_*HSL; o += 256) {
            int b = o >> 3, hc = o & 7;
            float gz = 0.f, gr = 0.f, gn = 0.f;
            #pragma unroll
            for (int s = 0; s < 4; s++) {
                gz += red[s*1536 + (hc     )*64 + b];
                gr += red[s*1536 + (8  + hc)*64 + b];
                gn += red[s*1536 + (16 + hc)*64 + b];
            }
            int hg = c0 + hc;
            const float* gx = g_GX + ((size_t)t*B_ + b)*G3;
            float z = sigf(gx[hg]        + gz);
            float r = sigf(gx[H_  + hg]  + gr);
            float n = tanhf(gx[2*H_ + hg] + r*gn);
            float mem = 0.f;
            #pragma unroll
            for (int kk = 0; kk < K_; kk++)
                mem = fmaf(wS[kk*8 + hc],
                           g_Hbuf[(size_t)(t + kk)*BH + (size_t)b*H_ + hg], mem);
            g_Hbuf[(size_t)(K_ + t)*BH + (size_t)b*H_ + hg] = (1.0f - z)*n + z*mem;
        }

        // grid barrier (monotonic counter, reset each launch by init_kernel)
        __threadfence();
        __syncthreads();
        if (tid == 0) {
            atomicAdd(&g_bar, 1u);
            unsigned target = (unsigned)NCTA * (unsigned)(t + 1);
            while (*(volatile unsigned*)&g_bar < target) { __nanosleep(64); }
        }
        __syncthreads();
    }
}

// ---------------- tail: write H_fin (last K states, oldest first) ----------------
__global__ void tail_kernel(float* __restrict__ outTail)
{
    const int n = K_*BH;
    for (int i = blockIdx.x*blockDim.x + threadIdx.x; i < n; i += gridDim.x*blockDim.x)
        outTail[i] = g_Hbuf[(size_t)T_*BH + i];
}

// ---------------- launch ----------------
extern "C" void kernel_launch(void* const* d_in, const int* in_sizes, int n_in,
                              void* d_out, int out_size)
{
    const float* inputs = (const float*)d_in[0];  // (T,B,I)
    const float* hidden = (const float*)d_in[1];  // (K,B,H)
    const float* Wx     = (const float*)d_in[2];  // (I,3H)
    const float* Wh     = (const float*)d_in[3];  // (H,3H)
    const float* b      = (const float*)d_in[4];  // (3H,)
    const float* Wo     = (const float*)d_in[5];  // (H,O)
    const float* bo     = (const float*)d_in[6];  // (O,)
    const float* mp     = (const float*)d_in[7];  // (1,H)
    float* out = (float*)d_out;

    void* gxp = nullptr; cudaGetSymbolAddress(&gxp, g_GX);
    void* hbp = nullptr; cudaGetSymbolAddress(&hbp, g_Hbuf);

    cudaFuncSetAttribute(recur_kernel, cudaFuncAttributeMaxDynamicSharedMemorySize, SMEM_BYTES);

    // 1. barrier reset + GL weights + initial hidden copy
    init_kernel<<<256, 256>>>(hidden, mp);

    // 2. GX = X @ Wx + b   (M=16384, N=3072, K=512)
    sgemm128<<<dim3(G3/128, (T_*B_)/128), 256>>>(inputs, Wx, b, (float*)gxp,
                                                 T_*B_, G3, I_);

    // 3. sequential recurrence (persistent, 256 steps)
    recur_kernel<<<NCTA, 256, SMEM_BYTES>>>(Wh);

    // 4. outs = H_all @ Wo + bo   (M=16384, N=512, K=1024)
    sgemm128<<<dim3(O_/128, (T_*B_)/128), 256>>>((const float*)hbp + (size_t)K_*BH,
                                                 Wo, bo, out, T_*B_, O_, H_);

    // 5. H_fin tail
    if (out_size >= TBO + K_*BH)
        tail_kernel<<<256, 256>>>(out + TBO);
}

// round 5
// speedup vs baseline: 1.2870x; 1.2820x over previous
#include <cuda_runtime.h>
#include <cstdint>
#include <cstddef>

// ---------------- problem constants ----------------
#define T_   256
#define B_   64
#define I_   512
#define H_   1024
#define O_   512
#define K_   8
#define G3   3072
#define BH   65536
#define TBO  8388608

// ---------------- recurrence config ----------------
#define NCTA 64        // persistent CTAs; each owns 16 h-cols x 3 gates (N=48)
// smem byte offsets
#define SMO_A0 0       // A chunk buf 0 (32768)
#define SMO_A1 32768
#define SMO_B0 65536   // B chunk buf 0 (24576)
#define SMO_B1 90112
#define SMO_GH 114688  // gh dump 64x48 fp32 (12288)
#define SMO_MB 126976  // 2 mbarriers
#define SMEM_REQ 127104

// ---------------- device scratch ----------------
__device__ float    g_GX[(size_t)T_*B_*G3];       // x@Wx+b
__device__ float    g_Hbuf[(size_t)(K_+T_)*BH];   // hidden ring fp32
__device__ float    g_w[K_*H_];                   // GL weights, idx0 oldest
__device__ float    g_AImg[2][BH];                // h in A-fragment-major order (tf32), ping-pong
__device__ float    g_BImg[(size_t)NCTA*49152];   // Wh in B-fragment-major order (tf32), 12MB
__device__ unsigned g_bar;

// ---------------- helpers ----------------
__device__ __forceinline__ uint32_t smem_u32(const void* p) {
    uint32_t a; asm("{ .reg .u64 t; cvta.to.shared.u64 t, %1; cvt.u32.u64 %0, t; }" : "=r"(a) : "l"(p));
    return a;
}
__device__ __forceinline__ void mbar_init(uint32_t m, uint32_t c) {
    asm volatile("mbarrier.init.shared.b64 [%0], %1;" :: "r"(m), "r"(c) : "memory");
}
__device__ __forceinline__ void mbar_expect_tx(uint32_t m, uint32_t bytes) {
    asm volatile("mbarrier.arrive.expect_tx.shared.b64 _, [%0], %1;" :: "r"(m), "r"(bytes) : "memory");
}
__device__ __forceinline__ void mbar_wait(uint32_t m, uint32_t parity) {
    asm volatile(
        "{\n\t.reg .pred P;\n\t"
        "WL_%=:\n\t"
        "mbarrier.try_wait.parity.acquire.cta.shared::cta.b64 P, [%0], %1, 0x989680;\n\t"
        "@P bra WD_%=;\n\t"
        "bra WL_%=;\n\t"
        "WD_%=:\n\t}"
        :: "r"(m), "r"(parity) : "memory");
}
__device__ __forceinline__ void bulk_g2s(uint32_t dst, const void* src, uint32_t bytes, uint32_t mbar) {
    asm volatile("cp.async.bulk.shared::cluster.global.mbarrier::complete_tx::bytes [%0], [%1], %2, [%3];"
                 :: "r"(dst), "l"(src), "r"(bytes), "r"(mbar) : "memory");
}
__device__ __forceinline__ void mma_tf32(float* d, const uint32_t* a, const uint32_t* b) {
    asm("mma.sync.aligned.m16n8k8.row.col.f32.tf32.tf32.f32 "
        "{%0,%1,%2,%3},{%4,%5,%6,%7},{%8,%9},{%0,%1,%2,%3};"
        : "+f"(d[0]), "+f"(d[1]), "+f"(d[2]), "+f"(d[3])
        : "r"(a[0]), "r"(a[1]), "r"(a[2]), "r"(a[3]), "r"(b[0]), "r"(b[1]));
}
__device__ __forceinline__ float to_tf32(float x) {
    float y; asm("cvt.rna.tf32.f32 %0, %1;" : "=f"(y) : "f"(x)); return y;
}
__device__ __forceinline__ float sigf(float x) { return 1.0f/(1.0f + __expf(-x)); }
__device__ __forceinline__ float tanhf_fast(float x) {
    float e = __expf(2.0f*x); return (e - 1.0f)/(e + 1.0f);
}

// A-fragment image index for value h[b][k]  (m16n8k8 .row A layout)
// AImg[((ks*4 + mt)*32 + lane)*4 + j], ks=k>>3, mt=b>>4
__device__ __forceinline__ int aimg_idx(int b, int k) {
    int ks = k >> 3, c7 = k & 7;
    int mt = b >> 4, r16 = b & 15;
    int g = r16 & 7, hi = r16 >> 3;
    int tg = c7 & 3, c4 = c7 >> 2;
    int lane = g*4 + tg;
    int j = hi + 2*c4;
    return ((ks*4 + mt)*32 + lane)*4 + j;
}

// ---------------- init: barrier + GL weights + hidden copy + A image[0] ----------------
__global__ void init_kernel(const float* __restrict__ hid, const float* __restrict__ mp)
{
    int idx = blockIdx.x*blockDim.x + threadIdx.x;
    int stride = gridDim.x*blockDim.x;
    if (idx == 0) g_bar = 0u;
    if (idx < H_) {
        float a = 0.5f / (1.0f + expf(-mp[idx]));
        float c = 1.0f;
        #pragma unroll
        for (int i = 0; i < K_; i++) {
            c *= ((float)i + a) / ((float)i + 1.0f);
            g_w[(K_-1-i)*H_ + idx] = c;
        }
    }
    for (int i = idx; i < K_*BH; i += stride) g_Hbuf[i] = hid[i];
    const float* h0 = hid + (size_t)(K_-1)*BH;   // most recent initial hidden
    for (int i = idx; i < BH; i += stride) {
        int b = i >> 10, k = i & 1023;
        g_AImg[0][aimg_idx(b, k)] = to_tf32(h0[(size_t)b*H_ + k]);
    }
}

// ---------------- prep: Wh -> B-fragment-major tf32 image ----------------
// CTA slice s owns cols {g*1024 + s*16 + hl}; local n = hl*3 + g (gates interleaved)
// BImg[(((s*128 + ks)*6 + nt)*32 + lane)*2 + j]  (m16n8k8 .col B layout)
__global__ void prep_wht(const float* __restrict__ Wh)
{
    int idx = blockIdx.x*blockDim.x + threadIdx.x;
    int stride = gridDim.x*blockDim.x;
    const int total = H_*G3;
    for (int i = idx; i < total; i += stride) {
        int k = i / G3, col = i - k*G3;
        int gate = col >> 10, cw = col & 1023;
        int s = cw >> 4, hl = cw & 15;
        int nl = hl*3 + gate;
        int nt = nl >> 3, g = nl & 7;
        int ks = k >> 3, tig = k & 3, j = (k >> 2) & 1;
        int lane = g*4 + tig;
        size_t dst = ((((size_t)s*128 + ks)*6 + nt)*32 + lane)*2 + j;
        g_BImg[dst] = to_tf32(Wh[i]);
    }
}

// ---------------- fp32 SGEMM (validated) ----------------
__global__ __launch_bounds__(256) void sgemm128(
    const float* __restrict__ A, const float* __restrict__ Bm,
    const float* __restrict__ bias, float* __restrict__ C,
    int M, int N, int Kd)
{
    __shared__ float As[8][128];
    __shared__ float Bs[8][128];
    const int tid  = threadIdx.x;
    const int bx   = blockIdx.x, by = blockIdx.y;
    const int trow = tid >> 4;
    const int tcol = tid & 15;

    float acc[8][8];
    #pragma unroll
    for (int i = 0; i < 8; i++)
        #pragma unroll
        for (int j = 0; j < 8; j++) acc[i][j] = 0.0f;

    const float* Ab = A  + (size_t)by*128*Kd;
    const float* Bb = Bm + (size_t)bx*128;
    const int arow = tid >> 1, acol = (tid & 1) << 2;
    const int brow = tid >> 5, bcol = (tid & 31) << 2;

    for (int k0 = 0; k0 < Kd; k0 += 8) {
        float4 av = *(const float4*)(Ab + (size_t)arow*Kd + k0 + acol);
        As[acol+0][arow] = av.x; As[acol+1][arow] = av.y;
        As[acol+2][arow] = av.z; As[acol+3][arow] = av.w;
        *(float4*)&Bs[brow][bcol] = *(const float4*)(Bb + (size_t)(k0 + brow)*N + bcol);
        __syncthreads();
        #pragma unroll
        for (int k = 0; k < 8; k++) {
            float4 a0 = *(float4*)&As[k][trow*8];
            float4 a1 = *(float4*)&As[k][trow*8 + 4];
            float4 b0 = *(float4*)&Bs[k][tcol*8];
            float4 b1 = *(float4*)&Bs[k][tcol*8 + 4];
            float ra[8] = {a0.x,a0.y,a0.z,a0.w,a1.x,a1.y,a1.z,a1.w};
            float rb[8] = {b0.x,b0.y,b0.z,b0.w,b1.x,b1.y,b1.z,b1.w};
            #pragma unroll
            for (int i = 0; i < 8; i++)
                #pragma unroll
                for (int j = 0; j < 8; j++)
                    acc[i][j] = fmaf(ra[i], rb[j], acc[i][j]);
        }
        __syncthreads();
    }

    #pragma unroll
    for (int i = 0; i < 8; i++) {
        int row = by*128 + trow*8 + i;
        float*       Cr = C    + (size_t)row*N + bx*128 + tcol*8;
        const float* br = bias + (size_t)bx*128 + tcol*8;
        #pragma unroll
        for (int j = 0; j < 8; j += 4) {
            float4 v;
            v.x = acc[i][j+0] + br[j+0];
            v.y = acc[i][j+1] + br[j+1];
            v.z = acc[i][j+2] + br[j+2];
            v.w = acc[i][j+3] + br[j+3];
            *(float4*)(Cr + j) = v;
        }
    }
}

// ---------------- persistent tf32-HMMA recurrence ----------------
extern __shared__ char smemRaw[];

__global__ __launch_bounds__(128, 1) void recur_mma()
{
    const int tid = threadIdx.x;
    const int w   = tid >> 5;        // warp 0..3
    const int l   = tid & 31;
    const int mw  = w >> 1;          // M half (rows 32*mw..)
    const int nw  = w & 1;           // N half (cols 24*nw..)
    const int s   = blockIdx.x;      // slice 0..63, h-cols s*16..s*16+15
    uint32_t smb  = smem_u32(smemRaw);
    uint32_t mb0  = smb + SMO_MB;
    uint32_t mb1  = smb + SMO_MB + 8;
    float* GH = (float*)(smemRaw + SMO_GH);

    if (tid == 0) { mbar_init(mb0, 1); mbar_init(mb1, 1); }
    __syncthreads();

    // per-thread epilogue constants: hl fixed by tid
    const int hl = tid & 15;
    const int hc = s*16 + hl;
    float wk[K_];
    #pragma unroll
    for (int kk = 0; kk < K_; kk++) wk[kk] = g_w[kk*H_ + hc];
    // A-image addressing constants for k = hc
    const int a_ks = hc >> 3, a_c7 = hc & 7;
    const int a_tg = a_c7 & 3, a_c4 = a_c7 >> 2;

    const char* bimg = (const char*)g_BImg + (size_t)s*196608;

    for (int t = 0; t < T_; t++) {
        const char* aimg = (const char*)g_AImg[t & 1];
        if (tid == 0) {
            mbar_expect_tx(mb0, 57344);
            bulk_g2s(smb + SMO_A0, aimg, 32768, mb0);
            bulk_g2s(smb + SMO_B0, bimg, 24576, mb0);
            mbar_expect_tx(mb1, 57344);
            bulk_g2s(smb + SMO_A1, aimg + 32768, 32768, mb1);
            bulk_g2s(smb + SMO_B1, bimg + 24576, 24576, mb1);
        }

        float acc[2][3][4];
        #pragma unroll
        for (int mi = 0; mi < 2; mi++)
            #pragma unroll
            for (int ni = 0; ni < 3; ni++)
                #pragma unroll
                for (int q = 0; q < 4; q++) acc[mi][ni][q] = 0.0f;

        #pragma unroll 1
        for (int c = 0; c < 8; c++) {
            const int bsel = c & 1;
            mbar_wait(bsel ? mb1 : mb0, (c >> 1) & 1);
            const char* Ab = smemRaw + (bsel ? SMO_A1 : SMO_A0);
            const char* Bb = smemRaw + (bsel ? SMO_B1 : SMO_B0);
            #pragma unroll
            for (int kl = 0; kl < 16; kl++) {
                uint32_t afr[2][4];
                *(uint4*)afr[0] = *(const uint4*)(Ab + ((size_t)((kl*4 + 2*mw    )*32 + l))*16);
                *(uint4*)afr[1] = *(const uint4*)(Ab + ((size_t)((kl*4 + 2*mw + 1)*32 + l))*16);
                uint32_t bfr[3][2];
                #pragma unroll
                for (int ni = 0; ni < 3; ni++)
                    *(uint2*)bfr[ni] = *(const uint2*)(Bb + ((size_t)((kl*6 + 3*nw + ni)*32 + l))*8);
                #pragma unroll
                for (int mi = 0; mi < 2; mi++)
                    #pragma unroll
                    for (int ni = 0; ni < 3; ni++)
                        mma_tf32(acc[mi][ni], afr[mi], bfr[ni]);
            }
            __syncthreads();
            if (tid == 0 && c < 6) {
                const int c2 = c + 2;
                uint32_t mb = bsel ? mb1 : mb0;
                mbar_expect_tx(mb, 57344);
                bulk_g2s(smb + (bsel ? SMO_A1 : SMO_A0), aimg + (size_t)c2*32768, 32768, mb);
                bulk_g2s(smb + (bsel ? SMO_B1 : SMO_B0), bimg + (size_t)c2*24576, 24576, mb);
            }
        }

        // ---- dump C fragments to smem: GH[b][n48] ----
        {
            const int g = l >> 2, tg2 = (l & 3)*2;
            #pragma unroll
            for (int mi = 0; mi < 2; mi++) {
                int row0 = (2*mw + mi)*16 + g;
                #pragma unroll
                for (int ni = 0; ni < 3; ni++) {
                    int colb = nw*24 + ni*8 + tg2;
                    *(float2*)&GH[row0*48 + colb]       = make_float2(acc[mi][ni][0], acc[mi][ni][1]);
                    *(float2*)&GH[(row0 + 8)*48 + colb] = make_float2(acc[mi][ni][2], acc[mi][ni][3]);
                }
            }
        }
        __syncthreads();

        // ---- gates + fractional memory (8 (b,hl) pairs per thread) ----
        float* imgn = g_AImg[(t + 1) & 1];
        #pragma unroll
        for (int i = 0; i < 8; i++) {
            int b = i*8 + (tid >> 4);
            float gz = GH[b*48 + hl*3 + 0];
            float gr = GH[b*48 + hl*3 + 1];
            float gn = GH[b*48 + hl*3 + 2];
            const float* gx = g_GX + ((size_t)t*B_ + b)*G3 + hc;
            float z = sigf(gx[0]      + gz);
            float r = sigf(gx[H_]     + gr);
            float n = tanhf_fast(gx[2*H_] + r*gn);
            float mem = 0.f;
            #pragma unroll
            for (int kk = 0; kk < K_; kk++)
                mem = fmaf(wk[kk], g_Hbuf[(size_t)(t + kk)*BH + (size_t)b*H_ + hc], mem);
            float hn = (1.0f - z)*n + z*mem;
            g_Hbuf[(size_t)(K_ + t)*BH + (size_t)b*H_ + hc] = hn;
            // A-image write for next step
            int mt = b >> 4, r16 = b & 15;
            int lane2 = (r16 & 7)*4 + a_tg;
            int j = (r16 >> 3) + 2*a_c4;
            imgn[((a_ks*4 + mt)*32 + lane2)*4 + j] = to_tf32(hn);
        }

        // ---- grid barrier ----
        __threadfence();
        __syncthreads();
        if (tid == 0) {
            atomicAdd(&g_bar, 1u);
            unsigned target = (unsigned)NCTA * (unsigned)(t + 1);
            while (*(volatile unsigned*)&g_bar < target) { __nanosleep(32); }
        }
        __syncthreads();
    }
}

// ---------------- tail ----------------
__global__ void tail_kernel(float* __restrict__ outTail)
{
    const int n = K_*BH;
    for (int i = blockIdx.x*blockDim.x + threadIdx.x; i < n; i += gridDim.x*blockDim.x)
        outTail[i] = g_Hbuf[(size_t)T_*BH + i];
}

// ---------------- launch ----------------
extern "C" void kernel_launch(void* const* d_in, const int* in_sizes, int n_in,
                              void* d_out, int out_size)
{
    const float* inputs = (const float*)d_in[0];
    const float* hidden = (const float*)d_in[1];
    const float* Wx     = (const float*)d_in[2];
    const float* Wh     = (const float*)d_in[3];
    const float* b      = (const float*)d_in[4];
    const float* Wo     = (const float*)d_in[5];
    const float* bo     = (const float*)d_in[6];
    const float* mp     = (const float*)d_in[7];
    float* out = (float*)d_out;

    void* gxp = nullptr; cudaGetSymbolAddress(&gxp, g_GX);
    void* hbp = nullptr; cudaGetSymbolAddress(&hbp, g_Hbuf);

    cudaFuncSetAttribute(recur_mma, cudaFuncAttributeMaxDynamicSharedMemorySize, SMEM_REQ);

    init_kernel<<<256, 256>>>(hidden, mp);
    prep_wht<<<512, 256>>>(Wh);
    sgemm128<<<dim3(G3/128, (T_*B_)/128), 256>>>(inputs, Wx, b, (float*)gxp,
                                                 T_*B_, G3, I_);
    recur_mma<<<NCTA, 128, SMEM_REQ>>>();
    sgemm128<<<dim3(O_/128, (T_*B_)/128), 256>>>((const float*)hbp + (size_t)K_*BH,
                                                 Wo, bo, out, T_*B_, O_, H_);
    if (out_size >= TBO + K_*BH)
        tail_kernel<<<256, 256>>>(out + TBO);
}

// round 6
// speedup vs baseline: 2.2447x; 1.7441x over previous
#include <cuda_runtime.h>
#include <cstdint>
#include <cstddef>

// ---------------- problem constants ----------------
#define T_   256
#define B_   64
#define I_   512
#define H_   1024
#define O_   512
#define K_   8
#define G3   3072
#define BH   65536
#define TBO  8388608

// ---------------- recurrence config ----------------
#define NCTA 64        // persistent CTAs; each owns 16 h-cols x 3 gates (N=48)
// smem byte offsets (dynamic)
#define SMO_A0   0        // A chunk buf 0 (32768)
#define SMO_A1   32768
#define SMO_B0   65536    // B chunk buf 0 (24576)
#define SMO_B1   90112
#define SMO_GH   114688   // gh dump 2 x 64x48 fp32 (24576)
#define SMO_HIST 139264   // h history ring 8x64x16 fp32 (32768)
#define SMO_MB   172032   // 2 mbarriers
#define SMEM_REQ 172160

// ---------------- device scratch ----------------
__device__ float    g_GX[(size_t)T_*B_*G3];       // x@Wx+b
__device__ float    g_Hbuf[(size_t)(K_+T_)*BH];   // hidden ring fp32
__device__ float    g_w[K_*H_];                   // GL weights, idx0 oldest
__device__ float    g_AImg[2][BH];                // h in A-fragment-major (tf32), ping-pong
__device__ float    g_BImg[(size_t)NCTA*49152];   // Wh in B-fragment-major (tf32), 12MB
__device__ float    g_WxImg[(size_t)I_*G3];       // Wx fragment-major (6MB)
__device__ float    g_WoImg[(size_t)H_*O_];       // Wo fragment-major (2MB)
__device__ unsigned g_bar;

// ---------------- helpers ----------------
__device__ __forceinline__ uint32_t smem_u32(const void* p) {
    uint32_t a; asm("{ .reg .u64 t; cvta.to.shared.u64 t, %1; cvt.u32.u64 %0, t; }" : "=r"(a) : "l"(p));
    return a;
}
__device__ __forceinline__ void mbar_init(uint32_t m, uint32_t c) {
    asm volatile("mbarrier.init.shared.b64 [%0], %1;" :: "r"(m), "r"(c) : "memory");
}
__device__ __forceinline__ void mbar_expect_tx(uint32_t m, uint32_t bytes) {
    asm volatile("mbarrier.arrive.expect_tx.shared.b64 _, [%0], %1;" :: "r"(m), "r"(bytes) : "memory");
}
__device__ __forceinline__ void mbar_wait(uint32_t m, uint32_t parity) {
    asm volatile(
        "{\n\t.reg .pred P;\n\t"
        "WL_%=:\n\t"
        "mbarrier.try_wait.parity.acquire.cta.shared::cta.b64 P, [%0], %1, 0x989680;\n\t"
        "@P bra WD_%=;\n\t"
        "bra WL_%=;\n\t"
        "WD_%=:\n\t}"
        :: "r"(m), "r"(parity) : "memory");
}
__device__ __forceinline__ void bulk_g2s(uint32_t dst, const void* src, uint32_t bytes, uint32_t mbar) {
    asm volatile("cp.async.bulk.shared::cluster.global.mbarrier::complete_tx::bytes [%0], [%1], %2, [%3];"
                 :: "r"(dst), "l"(src), "r"(bytes), "r"(mbar) : "memory");
}
__device__ __forceinline__ void cp16(uint32_t dst, const void* src) {
    asm volatile("cp.async.cg.shared.global [%0], [%1], 16;" :: "r"(dst), "l"(src));
}
__device__ __forceinline__ void cp_commit() { asm volatile("cp.async.commit_group;" ::: "memory"); }
__device__ __forceinline__ void cp_wait0() { asm volatile("cp.async.wait_group 0;" ::: "memory"); }
__device__ __forceinline__ void cp_wait1() { asm volatile("cp.async.wait_group 1;" ::: "memory"); }
__device__ __forceinline__ void mma_tf32(float* d, const uint32_t* a, const uint32_t* b) {
    asm("mma.sync.aligned.m16n8k8.row.col.f32.tf32.tf32.f32 "
        "{%0,%1,%2,%3},{%4,%5,%6,%7},{%8,%9},{%0,%1,%2,%3};"
        : "+f"(d[0]), "+f"(d[1]), "+f"(d[2]), "+f"(d[3])
        : "r"(a[0]), "r"(a[1]), "r"(a[2]), "r"(a[3]), "r"(b[0]), "r"(b[1]));
}
__device__ __forceinline__ float to_tf32(float x) {
    float y; asm("cvt.rna.tf32.f32 %0, %1;" : "=f"(y) : "f"(x)); return y;
}
__device__ __forceinline__ float sigf(float x) { return 1.0f/(1.0f + __expf(-x)); }
__device__ __forceinline__ float tanhf_fast(float x) {
    float e = __expf(2.0f*x); return (e - 1.0f)/(e + 1.0f);
}

// A-fragment image index for h[b][k]  (m16n8k8 .row A layout)
__device__ __forceinline__ int aimg_idx(int b, int k) {
    int ks = k >> 3, c7 = k & 7;
    int mt = b >> 4, r16 = b & 15;
    int g = r16 & 7, hi = r16 >> 3;
    int tg = c7 & 3, c4 = c7 >> 2;
    int lane = g*4 + tg;
    int j = hi + 2*c4;
    return ((ks*4 + mt)*32 + lane)*4 + j;
}

// ---------------- init ----------------
__global__ void init_kernel(const float* __restrict__ hid, const float* __restrict__ mp)
{
    int idx = blockIdx.x*blockDim.x + threadIdx.x;
    int stride = gridDim.x*blockDim.x;
    if (idx == 0) g_bar = 0u;
    if (idx < H_) {
        float a = 0.5f / (1.0f + expf(-mp[idx]));
        float c = 1.0f;
        #pragma unroll
        for (int i = 0; i < K_; i++) {
            c *= ((float)i + a) / ((float)i + 1.0f);
            g_w[(K_-1-i)*H_ + idx] = c;
        }
    }
    for (int i = idx; i < K_*BH; i += stride) g_Hbuf[i] = hid[i];
    const float* h0 = hid + (size_t)(K_-1)*BH;
    for (int i = idx; i < BH; i += stride) {
        int b = i >> 10, k = i & 1023;
        g_AImg[0][aimg_idx(b, k)] = to_tf32(h0[(size_t)b*H_ + k]);
    }
}

// ---------------- prep: Wh -> recurrence B-fragment image ----------------
__global__ void prep_wht(const float* __restrict__ Wh)
{
    int idx = blockIdx.x*blockDim.x + threadIdx.x;
    int stride = gridDim.x*blockDim.x;
    const int total = H_*G3;
    for (int i = idx; i < total; i += stride) {
        int k = i / G3, col = i - k*G3;
        int gate = col >> 10, cw = col & 1023;
        int s = cw >> 4, hl = cw & 15;
        int nl = hl*3 + gate;
        int nt = nl >> 3, g = nl & 7;
        int ks = k >> 3, tig = k & 3, j = (k >> 2) & 1;
        int lane = g*4 + tig;
        size_t dst = ((((size_t)s*128 + ks)*6 + nt)*32 + lane)*2 + j;
        g_BImg[dst] = to_tf32(Wh[i]);
    }
}

// ---------------- prep: generic weight -> GEMM B-fragment image ----------------
// layout: img[((((nb*KC + kc)*2 + ks)*16 + ntl)*32 + lane)*2 + j], KC = K/16
__global__ void prep_wimg(const float* __restrict__ W, float* __restrict__ img, int N, int K)
{
    int idx = blockIdx.x*blockDim.x + threadIdx.x;
    int stride = gridDim.x*blockDim.x;
    const int total = K*N, KC = K >> 4;
    for (int i = idx; i < total; i += stride) {
        int k = i / N, n = i - k*N;
        int nb = n >> 7, ntl = (n >> 3) & 15, g = n & 7;
        int kc = k >> 4, ks = (k >> 3) & 1, tq = k & 3, j = (k >> 2) & 1;
        int lane = g*4 + tq;
        size_t dst = ((((size_t)nb*KC + kc)*2 + ks)*16 + ntl)*32*2 + lane*2 + j;
        img[dst] = to_tf32(W[i]);
    }
}

// ---------------- tf32 HMMA GEMM: C = A @ W + bias ----------------
// A: MxK row-major fp32; Wimg: fragment-major image; C: MxN. 128x128 tile, K-chunk 16.
__global__ __launch_bounds__(256) void mma_gemm(
    const float* __restrict__ A, const float* __restrict__ Wimg,
    const float* __restrict__ bias, float* __restrict__ C,
    int M, int N, int K)
{
    __shared__ float As[2][128][20];   // pad 20 -> conflict-free A-frag gather
    __shared__ float Bs[2][2048];
    const int tid = threadIdx.x;
    const int w = tid >> 5, l = tid & 31;
    const int wm = w >> 1, wn = w & 1;      // 4 M-quarters x 2 N-halves
    const int bn = blockIdx.x, bm = blockIdx.y;
    const int KC = K >> 4;
    const int g = l >> 2, tq = l & 3;

    float acc[2][8][4];
    #pragma unroll
    for (int mi = 0; mi < 2; mi++)
        #pragma unroll
        for (int ni = 0; ni < 8; ni++)
            #pragma unroll
            for (int q = 0; q < 4; q++) acc[mi][ni][q] = 0.0f;

    const float* Bsrc = Wimg + (size_t)bn*KC*2048;
    const int arow = tid >> 2, aseg = tid & 3;   // +256: rows 64..127

    // prologue: chunk 0 -> buf 0
    {
        #pragma unroll
        for (int r = 0; r < 2; r++) {
            int row = arow + r*64;
            cp16(smem_u32(&As[0][row][aseg*4]), A + (size_t)(bm*128 + row)*K + aseg*4);
            cp16(smem_u32(&Bs[0][(tid + r*256)*4]), Bsrc + (size_t)(tid + r*256)*4);
        }
        cp_commit();
    }

    int buf = 0;
    for (int kc = 0; kc < KC; kc++) {
        if (kc + 1 < KC) {
            #pragma unroll
            for (int r = 0; r < 2; r++) {
                int row = arow + r*64;
                cp16(smem_u32(&As[buf^1][row][aseg*4]),
                     A + (size_t)(bm*128 + row)*K + (kc+1)*16 + aseg*4);
                cp16(smem_u32(&Bs[buf^1][(tid + r*256)*4]),
                     Bsrc + (size_t)(kc+1)*2048 + (tid + r*256)*4);
            }
            cp_commit();
            cp_wait1();
        } else {
            cp_wait0();
        }
        __syncthreads();

        #pragma unroll
        for (int ks = 0; ks < 2; ks++) {
            uint32_t afr[2][4];
            #pragma unroll
            for (int mi = 0; mi < 2; mi++) {
                int r0 = wm*32 + mi*16 + g;
                afr[mi][0] = __float_as_uint(to_tf32(As[buf][r0    ][ks*8 + tq    ]));
                afr[mi][1] = __float_as_uint(to_tf32(As[buf][r0 + 8][ks*8 + tq    ]));
                afr[mi][2] = __float_as_uint(to_tf32(As[buf][r0    ][ks*8 + tq + 4]));
                afr[mi][3] = __float_as_uint(to_tf32(As[buf][r0 + 8][ks*8 + tq + 4]));
            }
            #pragma unroll
            for (int ni = 0; ni < 8; ni++) {
                float2 bv = *(const float2*)&Bs[buf][((ks*16 + wn*8 + ni)*32 + l)*2];
                uint32_t bfr[2] = { __float_as_uint(bv.x), __float_as_uint(bv.y) };
                #pragma unroll
                for (int mi = 0; mi < 2; mi++)
                    mma_tf32(acc[mi][ni], afr[mi], bfr);
            }
        }
        __syncthreads();
        buf ^= 1;
    }

    #pragma unroll
    for (int mi = 0; mi < 2; mi++) {
        int row0 = bm*128 + wm*32 + mi*16 + g;
        #pragma unroll
        for (int ni = 0; ni < 8; ni++) {
            int col = bn*128 + wn*64 + ni*8 + tq*2;
            float b0 = bias[col], b1 = bias[col+1];
            *(float2*)&C[(size_t)row0*N + col] =
                make_float2(acc[mi][ni][0] + b0, acc[mi][ni][1] + b1);
            *(float2*)&C[(size_t)(row0 + 8)*N + col] =
                make_float2(acc[mi][ni][2] + b0, acc[mi][ni][3] + b1);
        }
    }
}

// ---------------- persistent tf32-HMMA recurrence (v2: 256 thr, k-split, smem hist) ----------------
extern __shared__ char smemRaw[];

__global__ __launch_bounds__(256, 1) void recur_mma()
{
    const int tid = threadIdx.x;
    const int w   = tid >> 5;
    const int l   = tid & 31;
    const int nw  = w & 1;           // N half (cols 24*nw..)
    const int mw  = (w >> 1) & 1;    // M half (rows 32*mw..)
    const int ksp = w >> 2;          // K split 0/1
    const int s   = blockIdx.x;      // slice: h-cols s*16..s*16+15
    uint32_t smb  = smem_u32(smemRaw);
    uint32_t mb0  = smb + SMO_MB;
    uint32_t mb1  = smb + SMO_MB + 8;
    float* GH0  = (float*)(smemRaw + SMO_GH);
    float* GH1  = GH0 + 3072;
    float* hist = (float*)(smemRaw + SMO_HIST);   // [8][64][16]

    if (tid == 0) { mbar_init(mb0, 1); mbar_init(mb1, 1); }
    __syncthreads();

    const int hl   = tid & 15;
    const int brow = tid >> 4;       // 0..15
    const int hc   = s*16 + hl;
    float wk[K_];
    #pragma unroll
    for (int kk = 0; kk < K_; kk++) wk[kk] = g_w[kk*H_ + hc];
    const int a_ks = hc >> 3, a_c7 = hc & 7;
    const int a_tg = a_c7 & 3, a_c4 = a_c7 >> 2;

    // hist ring init: hist[k][b][hl] = initial hidden slot k
    for (int i = tid; i < K_*B_*16; i += 256) {
        int k = i >> 10, rem = i & 1023;
        int b = rem >> 4, h2 = rem & 15;
        hist[i] = g_Hbuf[(size_t)k*BH + (size_t)b*H_ + s*16 + h2];
    }
    __syncthreads();

    const char* bimg = (const char*)g_BImg + (size_t)s*196608;

    for (int t = 0; t < T_; t++) {
        const char* aimg = (const char*)g_AImg[t & 1];
        if (tid == 0) {
            mbar_expect_tx(mb0, 57344);
            bulk_g2s(smb + SMO_A0, aimg, 32768, mb0);
            bulk_g2s(smb + SMO_B0, bimg, 24576, mb0);
            mbar_expect_tx(mb1, 57344);
            bulk_g2s(smb + SMO_A1, aimg + 32768, 32768, mb1);
            bulk_g2s(smb + SMO_B1, bimg + 24576, 24576, mb1);
        }

        float acc[2][3][4];
        #pragma unroll
        for (int mi = 0; mi < 2; mi++)
            #pragma unroll
            for (int ni = 0; ni < 3; ni++)
                #pragma unroll
                for (int q = 0; q < 4; q++) acc[mi][ni][q] = 0.0f;

        #pragma unroll 1
        for (int c = 0; c < 8; c++) {
            const int bsel = c & 1;
            mbar_wait(bsel ? mb1 : mb0, (c >> 1) & 1);
            const char* Ab = smemRaw + (bsel ? SMO_A1 : SMO_A0);
            const char* Bb = smemRaw + (bsel ? SMO_B1 : SMO_B0);
            #pragma unroll
            for (int j = 0; j < 8; j++) {
                const int kl = ksp*8 + j;
                uint32_t afr[2][4];
                *(uint4*)afr[0] = *(const uint4*)(Ab + ((size_t)((kl*4 + 2*mw    )*32 + l))*16);
                *(uint4*)afr[1] = *(const uint4*)(Ab + ((size_t)((kl*4 + 2*mw + 1)*32 + l))*16);
                uint32_t bfr[3][2];
                #pragma unroll
                for (int ni = 0; ni < 3; ni++)
                    *(uint2*)bfr[ni] = *(const uint2*)(Bb + ((size_t)((kl*6 + 3*nw + ni)*32 + l))*8);
                #pragma unroll
                for (int mi = 0; mi < 2; mi++)
                    #pragma unroll
                    for (int ni = 0; ni < 3; ni++)
                        mma_tf32(acc[mi][ni], afr[mi], bfr[ni]);
            }
            __syncthreads();
            if (tid == 0 && c < 6) {
                const int c2 = c + 2;
                uint32_t mb = bsel ? mb1 : mb0;
                mbar_expect_tx(mb, 57344);
                bulk_g2s(smb + (bsel ? SMO_A1 : SMO_A0), aimg + (size_t)c2*32768, 32768, mb);
                bulk_g2s(smb + (bsel ? SMO_B1 : SMO_B0), bimg + (size_t)c2*24576, 24576, mb);
            }
        }

        // dump C fragments: GH[ksp][b][n48]
        {
            float* GH = ksp ? GH1 : GH0;
            const int gg = l >> 2, tg2 = (l & 3)*2;
            #pragma unroll
            for (int mi = 0; mi < 2; mi++) {
                int row0 = (2*mw + mi)*16 + gg;
                #pragma unroll
                for (int ni = 0; ni < 3; ni++) {
                    int colb = nw*24 + ni*8 + tg2;
                    *(float2*)&GH[row0*48 + colb]       = make_float2(acc[mi][ni][0], acc[mi][ni][1]);
                    *(float2*)&GH[(row0 + 8)*48 + colb] = make_float2(acc[mi][ni][2], acc[mi][ni][3]);
                }
            }
        }
        __syncthreads();

        // gates + fractional memory (4 (b,hl) pairs per thread)
        float* imgn = g_AImg[(t + 1) & 1];
        #pragma unroll
        for (int i = 0; i < 4; i++) {
            int b = i*16 + brow;
            int gi = b*48 + hl*3;
            float gz = GH0[gi    ] + GH1[gi    ];
            float gr = GH0[gi + 1] + GH1[gi + 1];
            float gn = GH0[gi + 2] + GH1[gi + 2];
            const float* gx = g_GX + ((size_t)t*B_ + b)*G3 + hc;
            float z = sigf(gx[0]      + gz);
            float r = sigf(gx[H_]     + gr);
            float n = tanhf_fast(gx[2*H_] + r*gn);
            float mem = 0.f;
            #pragma unroll
            for (int kk = 0; kk < K_; kk++)
                mem = fmaf(wk[kk], hist[((t + kk) & 7)*1024 + b*16 + hl], mem);
            float hn = (1.0f - z)*n + z*mem;
            hist[(t & 7)*1024 + b*16 + hl] = hn;
            g_Hbuf[(size_t)(K_ + t)*BH + (size_t)b*H_ + hc] = hn;
            int mt = b >> 4, r16 = b & 15;
            int lane2 = (r16 & 7)*4 + a_tg;
            int j = (r16 >> 3) + 2*a_c4;
            imgn[((a_ks*4 + mt)*32 + lane2)*4 + j] = to_tf32(hn);
        }

        // grid barrier
        __threadfence();
        __syncthreads();
        if (tid == 0) {
            atomicAdd(&g_bar, 1u);
            unsigned target = (unsigned)NCTA * (unsigned)(t + 1);
            while (*(volatile unsigned*)&g_bar < target) { __nanosleep(32); }
        }
        __syncthreads();
    }
}

// ---------------- tail ----------------
__global__ void tail_kernel(float* __restrict__ outTail)
{
    const int n = K_*BH;
    for (int i = blockIdx.x*blockDim.x + threadIdx.x; i < n; i += gridDim.x*blockDim.x)
        outTail[i] = g_Hbuf[(size_t)T_*BH + i];
}

// ---------------- launch ----------------
extern "C" void kernel_launch(void* const* d_in, const int* in_sizes, int n_in,
                              void* d_out, int out_size)
{
    const float* inputs = (const float*)d_in[0];
    const float* hidden = (const float*)d_in[1];
    const float* Wx     = (const float*)d_in[2];
    const float* Wh     = (const float*)d_in[3];
    const float* b      = (const float*)d_in[4];
    const float* Wo     = (const float*)d_in[5];
    const float* bo     = (const float*)d_in[6];
    const float* mp     = (const float*)d_in[7];
    float* out = (float*)d_out;

    void* gxp = nullptr; cudaGetSymbolAddress(&gxp, g_GX);
    void* hbp = nullptr; cudaGetSymbolAddress(&hbp, g_Hbuf);
    void* wxi = nullptr; cudaGetSymbolAddress(&wxi, g_WxImg);
    void* woi = nullptr; cudaGetSymbolAddress(&woi, g_WoImg);

    cudaFuncSetAttribute(recur_mma, cudaFuncAttributeMaxDynamicSharedMemorySize, SMEM_REQ);

    init_kernel<<<256, 256>>>(hidden, mp);
    prep_wht<<<512, 256>>>(Wh);
    prep_wimg<<<512, 256>>>(Wx, (float*)wxi, G3, I_);
    prep_wimg<<<512, 256>>>(Wo, (float*)woi, O_, H_);

    // GX = X @ Wx + b
    mma_gemm<<<dim3(G3/128, (T_*B_)/128), 256>>>(inputs, (const float*)wxi, b,
                                                 (float*)gxp, T_*B_, G3, I_);
    // recurrence
    recur_mma<<<NCTA, 256, SMEM_REQ>>>();
    // outs = H_all @ Wo + bo
    mma_gemm<<<dim3(O_/128, (T_*B_)/128), 256>>>((const float*)hbp + (size_t)K_*BH,
                                                 (const float*)woi, bo, out,
                                                 T_*B_, O_, H_);
    if (out_size >= TBO + K_*BH)
        tail_kernel<<<256, 256>>>(out + TBO);
}

// round 7
// speedup vs baseline: 4.3076x; 1.9191x over previous
#include <cuda_runtime.h>
#include <cstdint>
#include <cstddef>

// ---------------- problem constants ----------------
#define T_   256
#define B_   64
#define I_   512
#define H_   1024
#define O_   512
#define K_   8
#define G3   3072
#define BH   65536
#define TBO  8388608

// ---------------- recurrence config ----------------
#define NCTA 128        // persistent CTAs; each owns 8 h-cols x 3 gates (N=24)
// smem byte offsets (dynamic)
#define SMO_BRES 0          // resident Wh B-image: 98304
#define SMO_ABUF 98304      // 3 x 32768 A chunk ring
#define SMO_GH   98304      // GH alias on A buf 0 (4x64x24 fp32 = 24576), used post-loop only
#define SMO_GXS  196608     // gx slice stage: 6144
#define SMO_HIST 202752     // h history ring 8x64x8 fp32 = 16384
#define SMO_MB   219136     // mbarriers: full[3]@0, cons[3]@24, gx@48, bres@56
#define SMEM_REQ 219264

// ---------------- device scratch ----------------
__device__ float    g_GX2[(size_t)T_*NCTA*B_*24];  // gate preact, slice-major (201MB)
__device__ float    g_Hbuf[(size_t)(K_+T_)*BH];    // hidden ring fp32
__device__ float    g_w[K_*H_];                    // GL weights, idx0 oldest
__device__ float    g_AImg[2][BH];                 // h in A-fragment-major (tf32), ping-pong
__device__ float    g_BImg[(size_t)NCTA*24576];    // Wh B-fragment-major (tf32), 12MB
__device__ float    g_WxImg[(size_t)I_*G3];        // Wx fragment-major (6MB)
__device__ float    g_WoImg[(size_t)H_*O_];        // Wo fragment-major (2MB)
__device__ unsigned g_bar;

// ---------------- helpers ----------------
__device__ __forceinline__ uint32_t smem_u32(const void* p) {
    uint32_t a; asm("{ .reg .u64 t; cvta.to.shared.u64 t, %1; cvt.u32.u64 %0, t; }" : "=r"(a) : "l"(p));
    return a;
}
__device__ __forceinline__ void mbar_init(uint32_t m, uint32_t c) {
    asm volatile("mbarrier.init.shared.b64 [%0], %1;" :: "r"(m), "r"(c) : "memory");
}
__device__ __forceinline__ void mbar_arrive(uint32_t m) {
    asm volatile("mbarrier.arrive.shared.b64 _, [%0];" :: "r"(m) : "memory");
}
__device__ __forceinline__ void mbar_expect_tx(uint32_t m, uint32_t bytes) {
    asm volatile("mbarrier.arrive.expect_tx.shared.b64 _, [%0], %1;" :: "r"(m), "r"(bytes) : "memory");
}
__device__ __forceinline__ void mbar_wait(uint32_t m, uint32_t parity) {
    asm volatile(
        "{\n\t.reg .pred P;\n\t"
        "WL_%=:\n\t"
        "mbarrier.try_wait.parity.acquire.cta.shared::cta.b64 P, [%0], %1, 0x989680;\n\t"
        "@P bra WD_%=;\n\t"
        "bra WL_%=;\n\t"
        "WD_%=:\n\t}"
        :: "r"(m), "r"(parity) : "memory");
}
__device__ __forceinline__ void bulk_g2s(uint32_t dst, const void* src, uint32_t bytes, uint32_t mbar) {
    asm volatile("cp.async.bulk.shared::cluster.global.mbarrier::complete_tx::bytes [%0], [%1], %2, [%3];"
                 :: "r"(dst), "l"(src), "r"(bytes), "r"(mbar) : "memory");
}
__device__ __forceinline__ void cp16(uint32_t dst, const void* src) {
    asm volatile("cp.async.cg.shared.global [%0], [%1], 16;" :: "r"(dst), "l"(src));
}
__device__ __forceinline__ void cp_commit() { asm volatile("cp.async.commit_group;" ::: "memory"); }
__device__ __forceinline__ void cp_wait0() { asm volatile("cp.async.wait_group 0;" ::: "memory"); }
__device__ __forceinline__ void cp_wait1() { asm volatile("cp.async.wait_group 1;" ::: "memory"); }
__device__ __forceinline__ void mma_tf32(float* d, const uint32_t* a, const uint32_t* b) {
    asm("mma.sync.aligned.m16n8k8.row.col.f32.tf32.tf32.f32 "
        "{%0,%1,%2,%3},{%4,%5,%6,%7},{%8,%9},{%0,%1,%2,%3};"
        : "+f"(d[0]), "+f"(d[1]), "+f"(d[2]), "+f"(d[3])
        : "r"(a[0]), "r"(a[1]), "r"(a[2]), "r"(a[3]), "r"(b[0]), "r"(b[1]));
}
__device__ __forceinline__ float to_tf32(float x) {
    float y; asm("cvt.rna.tf32.f32 %0, %1;" : "=f"(y) : "f"(x)); return y;
}
__device__ __forceinline__ float sigf(float x) { return 1.0f/(1.0f + __expf(-x)); }
__device__ __forceinline__ float tanhf_fast(float x) {
    float e = __expf(2.0f*x); return (e - 1.0f)/(e + 1.0f);
}

// A-fragment image index for h[b][k]  (m16n8k8 .row A layout)
__device__ __forceinline__ int aimg_idx(int b, int k) {
    int ks = k >> 3, c7 = k & 7;
    int mt = b >> 4, r16 = b & 15;
    int g = r16 & 7, hi = r16 >> 3;
    int tg = c7 & 3, c4 = c7 >> 2;
    int lane = g*4 + tg;
    int j = hi + 2*c4;
    return ((ks*4 + mt)*32 + lane)*4 + j;
}

// ---------------- init ----------------
__global__ void init_kernel(const float* __restrict__ hid, const float* __restrict__ mp)
{
    int idx = blockIdx.x*blockDim.x + threadIdx.x;
    int stride = gridDim.x*blockDim.x;
    if (idx == 0) g_bar = 0u;
    if (idx < H_) {
        float a = 0.5f / (1.0f + expf(-mp[idx]));
        float c = 1.0f;
        #pragma unroll
        for (int i = 0; i < K_; i++) {
            c *= ((float)i + a) / ((float)i + 1.0f);
            g_w[(K_-1-i)*H_ + idx] = c;
        }
    }
    for (int i = idx; i < K_*BH; i += stride) g_Hbuf[i] = hid[i];
    const float* h0 = hid + (size_t)(K_-1)*BH;
    for (int i = idx; i < BH; i += stride) {
        int b = i >> 10, k = i & 1023;
        g_AImg[0][aimg_idx(b, k)] = to_tf32(h0[(size_t)b*H_ + k]);
    }
}

// ---------------- prep: Wh -> recurrence B-fragment image (slice = 8 h-cols) ----------------
__global__ void prep_wht(const float* __restrict__ Wh)
{
    int idx = blockIdx.x*blockDim.x + threadIdx.x;
    int stride = gridDim.x*blockDim.x;
    const int total = H_*G3;
    for (int i = idx; i < total; i += stride) {
        int k = i / G3, col = i - k*G3;
        int gate = col >> 10, cw = col & 1023;
        int s = cw >> 3, hl8 = cw & 7;
        int nl = hl8*3 + gate;                 // 0..23
        int nt = nl >> 3, gl = nl & 7;
        int ks = k >> 3, tig = k & 3, j = (k >> 2) & 1;
        int lane = gl*4 + tig;
        size_t dst = ((((size_t)s*128 + ks)*3 + nt)*32 + lane)*2 + j;
        g_BImg[dst] = to_tf32(Wh[i]);
    }
}

// ---------------- prep: generic weight -> GEMM B-fragment image ----------------
__global__ void prep_wimg(const float* __restrict__ W, float* __restrict__ img, int N, int K)
{
    int idx = blockIdx.x*blockDim.x + threadIdx.x;
    int stride = gridDim.x*blockDim.x;
    const int total = K*N, KC = K >> 4;
    for (int i = idx; i < total; i += stride) {
        int k = i / N, n = i - k*N;
        int nb = n >> 7, ntl = (n >> 3) & 15, g = n & 7;
        int kc = k >> 4, ks = (k >> 3) & 1, tq = k & 3, j = (k >> 2) & 1;
        int lane = g*4 + tq;
        size_t dst = ((((size_t)nb*KC + kc)*2 + ks)*16 + ntl)*32*2 + lane*2 + j;
        img[dst] = to_tf32(W[i]);
    }
}

// ---------------- tf32 HMMA GEMM: C = A @ W + bias ----------------
// mode 0: C row-major MxN.  mode 1: write GX2[t][slice][b][gate*8+hl8] layout.
__global__ __launch_bounds__(256) void mma_gemm(
    const float* __restrict__ A, const float* __restrict__ Wimg,
    const float* __restrict__ bias, float* __restrict__ C,
    int M, int N, int K, int mode)
{
    __shared__ float As[2][128][20];
    __shared__ float Bs[2][2048];
    const int tid = threadIdx.x;
    const int w = tid >> 5, l = tid & 31;
    const int wm = w >> 1, wn = w & 1;
    const int bn = blockIdx.x, bm = blockIdx.y;
    const int KC = K >> 4;
    const int g = l >> 2, tq = l & 3;

    float acc[2][8][4];
    #pragma unroll
    for (int mi = 0; mi < 2; mi++)
        #pragma unroll
        for (int ni = 0; ni < 8; ni++)
            #pragma unroll
            for (int q = 0; q < 4; q++) acc[mi][ni][q] = 0.0f;

    const float* Bsrc = Wimg + (size_t)bn*KC*2048;
    const int arow = tid >> 2, aseg = tid & 3;

    {
        #pragma unroll
        for (int r = 0; r < 2; r++) {
            int row = arow + r*64;
            cp16(smem_u32(&As[0][row][aseg*4]), A + (size_t)(bm*128 + row)*K + aseg*4);
            cp16(smem_u32(&Bs[0][(tid + r*256)*4]), Bsrc + (size_t)(tid + r*256)*4);
        }
        cp_commit();
    }

    int buf = 0;
    for (int kc = 0; kc < KC; kc++) {
        if (kc + 1 < KC) {
            #pragma unroll
            for (int r = 0; r < 2; r++) {
                int row = arow + r*64;
                cp16(smem_u32(&As[buf^1][row][aseg*4]),
                     A + (size_t)(bm*128 + row)*K + (kc+1)*16 + aseg*4);
                cp16(smem_u32(&Bs[buf^1][(tid + r*256)*4]),
                     Bsrc + (size_t)(kc+1)*2048 + (tid + r*256)*4);
            }
            cp_commit();
            cp_wait1();
        } else {
            cp_wait0();
        }
        __syncthreads();

        #pragma unroll
        for (int ks = 0; ks < 2; ks++) {
            uint32_t afr[2][4];
            #pragma unroll
            for (int mi = 0; mi < 2; mi++) {
                int r0 = wm*32 + mi*16 + g;
                afr[mi][0] = __float_as_uint(to_tf32(As[buf][r0    ][ks*8 + tq    ]));
                afr[mi][1] = __float_as_uint(to_tf32(As[buf][r0 + 8][ks*8 + tq    ]));
                afr[mi][2] = __float_as_uint(to_tf32(As[buf][r0    ][ks*8 + tq + 4]));
                afr[mi][3] = __float_as_uint(to_tf32(As[buf][r0 + 8][ks*8 + tq + 4]));
            }
            #pragma unroll
            for (int ni = 0; ni < 8; ni++) {
                float2 bv = *(const float2*)&Bs[buf][((ks*16 + wn*8 + ni)*32 + l)*2];
                uint32_t bfr[2] = { __float_as_uint(bv.x), __float_as_uint(bv.y) };
                #pragma unroll
                for (int mi = 0; mi < 2; mi++)
                    mma_tf32(acc[mi][ni], afr[mi], bfr);
            }
        }
        __syncthreads();
        buf ^= 1;
    }

    #pragma unroll
    for (int mi = 0; mi < 2; mi++) {
        int row0 = bm*128 + wm*32 + mi*16 + g;
        #pragma unroll
        for (int ni = 0; ni < 8; ni++) {
            int col = bn*128 + wn*64 + ni*8 + tq*2;
            float b0 = bias[col], b1 = bias[col+1];
            if (mode == 0) {
                *(float2*)&C[(size_t)row0*N + col] =
                    make_float2(acc[mi][ni][0] + b0, acc[mi][ni][1] + b1);
                *(float2*)&C[(size_t)(row0 + 8)*N + col] =
                    make_float2(acc[mi][ni][2] + b0, acc[mi][ni][3] + b1);
            } else {
                int gate = col >> 10, cw = col & 1023;
                int s2 = cw >> 3, hl = cw & 7;
                int tt = row0 >> 6, bb = row0 & 63;
                size_t base = ((size_t)tt*NCTA + s2)*64;
                *(float2*)&C[(base + bb)*24 + gate*8 + hl] =
                    make_float2(acc[mi][ni][0] + b0, acc[mi][ni][1] + b1);
                *(float2*)&C[(base + bb + 8)*24 + gate*8 + hl] =
                    make_float2(acc[mi][ni][2] + b0, acc[mi][ni][3] + b1);
            }
        }
    }
}

// ---------------- persistent tf32-HMMA recurrence v3 ----------------
// 128 CTAs, N=24/CTA, Wh resident in smem, 3-deep A ring, GX prefetch.
extern __shared__ char smemRaw[];

__global__ __launch_bounds__(256, 1) void recur_mma()
{
    const int tid = threadIdx.x;
    const int w   = tid >> 5;
    const int l   = tid & 31;
    const int mw  = w & 1;           // M half: mt = 2*mw + mi
    const int ksp = w >> 1;          // K split 0..3
    const int s   = blockIdx.x;      // slice: h-cols s*8..s*8+7
    uint32_t smb  = smem_u32(smemRaw);
    uint32_t mbF0 = smb + SMO_MB;        // full[i] @ +8i
    uint32_t mbC0 = smb + SMO_MB + 24;   // cons[i] @ +8i
    uint32_t mbGX = smb + SMO_MB + 48;
    uint32_t mbBR = smb + SMO_MB + 56;
    float* Bres = (float*)(smemRaw + SMO_BRES);
    float* GH   = (float*)(smemRaw + SMO_GH);
    float* gxs  = (float*)(smemRaw + SMO_GXS);
    float* hist = (float*)(smemRaw + SMO_HIST);

    if (tid == 0) {
        #pragma unroll
        for (int i = 0; i < 3; i++) { mbar_init(mbF0 + 8*i, 1); mbar_init(mbC0 + 8*i, 8); }
        mbar_init(mbGX, 1); mbar_init(mbBR, 1);
    }
    __syncthreads();
    if (tid == 0) {
        mbar_expect_tx(mbBR, 98304);
        bulk_g2s(smb + SMO_BRES, (const char*)g_BImg + (size_t)s*98304, 98304, mbBR);
    }

    // hist ring init: hist[k][b][h8]
    for (int i = tid; i < K_*B_*8; i += 256) {
        int k = i >> 9, b = (i >> 3) & 63, h2 = i & 7;
        hist[i] = g_Hbuf[(size_t)k*BH + (size_t)b*H_ + s*8 + h2];
    }

    // epilogue constants
    const int hl8  = tid & 7;
    const int brow = tid >> 3;       // 0..31; b = brow, brow+32
    const int hc   = s*8 + hl8;
    float wk[K_];
    #pragma unroll
    for (int kk = 0; kk < K_; kk++) wk[kk] = g_w[kk*H_ + hc];
    const int a_tg = hl8 & 3, a_c4 = hl8 >> 2;
    const int gg = l >> 2, tq = l & 3;

    mbar_wait(mbBR, 0);
    __syncthreads();

    for (int t = 0; t < T_; t++) {
        const char* aimg = (const char*)g_AImg[t & 1];
        if (tid == 0) {
            mbar_expect_tx(mbGX, 6144);
            bulk_g2s(smb + SMO_GXS,
                     g_GX2 + (((size_t)t*NCTA + s)*64)*24, 6144, mbGX);
            #pragma unroll
            for (int cp = 0; cp < 3; cp++) {
                int gc = t*8 + cp, buf = gc % 3, f = gc / 3;
                if (f > 0) mbar_wait(mbC0 + 8*buf, (f - 1) & 1);
                mbar_expect_tx(mbF0 + 8*buf, 32768);
                bulk_g2s(smb + SMO_ABUF + buf*32768, aimg + (size_t)cp*32768, 32768, mbF0 + 8*buf);
            }
        }

        float acc[2][3][4];
        #pragma unroll
        for (int mi = 0; mi < 2; mi++)
            #pragma unroll
            for (int ni = 0; ni < 3; ni++)
                #pragma unroll
                for (int q = 0; q < 4; q++) acc[mi][ni][q] = 0.0f;

        #pragma unroll 1
        for (int c = 0; c < 8; c++) {
            const int gc = t*8 + c, buf = gc % 3, f = gc / 3;
            mbar_wait(mbF0 + 8*buf, f & 1);
            const char* Ab = smemRaw + SMO_ABUF + buf*32768;
            #pragma unroll
            for (int kl = 0; kl < 4; kl++) {
                const int ksl = ksp*4 + kl;          // local ks 0..15
                const int ksg = c*16 + ksl;          // global ks 0..127
                uint32_t afr[2][4];
                *(uint4*)afr[0] = *(const uint4*)(Ab + ((size_t)((ksl*4 + 2*mw    )*32 + l))*16);
                *(uint4*)afr[1] = *(const uint4*)(Ab + ((size_t)((ksl*4 + 2*mw + 1)*32 + l))*16);
                #pragma unroll
                for (int ni = 0; ni < 3; ni++) {
                    float2 bv = *(const float2*)&Bres[((ksg*3 + ni)*32 + l)*2];
                    uint32_t bfr[2] = { __float_as_uint(bv.x), __float_as_uint(bv.y) };
                    #pragma unroll
                    for (int mi = 0; mi < 2; mi++)
                        mma_tf32(acc[mi][ni], afr[mi], bfr);
                }
            }
            __syncwarp();
            if (l == 0) mbar_arrive(mbC0 + 8*buf);
            if (tid == 0 && c < 5) {
                int gc2 = gc + 3, buf2 = gc2 % 3, f2 = gc2 / 3;
                mbar_wait(mbC0 + 8*buf2, (f2 - 1) & 1);
                mbar_expect_tx(mbF0 + 8*buf2, 32768);
                bulk_g2s(smb + SMO_ABUF + buf2*32768, aimg + (size_t)(c + 3)*32768, 32768, mbF0 + 8*buf2);
            }
        }
        __syncthreads();   // all buffer reads done -> GH alias safe

        // dump C fragments: GH[ksp][b][24]
        #pragma unroll
        for (int mi = 0; mi < 2; mi++) {
            int row0 = (2*mw + mi)*16 + gg;
            #pragma unroll
            for (int ni = 0; ni < 3; ni++) {
                int colb = ni*8 + tq*2;
                *(float2*)&GH[ksp*1536 + row0*24 + colb]       = make_float2(acc[mi][ni][0], acc[mi][ni][1]);
                *(float2*)&GH[ksp*1536 + (row0 + 8)*24 + colb] = make_float2(acc[mi][ni][2], acc[mi][ni][3]);
            }
        }
        __syncthreads();
        mbar_wait(mbGX, t & 1);

        // gates + fractional memory (2 (b,hl8) pairs per thread)
        float* imgn = g_AImg[(t + 1) & 1];
        #pragma unroll
        for (int i = 0; i < 2; i++) {
            int b = brow + i*32;
            int gi = b*24 + hl8*3;
            float gz = GH[gi] + GH[1536 + gi] + GH[3072 + gi] + GH[4608 + gi];
            float gr = GH[gi+1] + GH[1536 + gi+1] + GH[3072 + gi+1] + GH[4608 + gi+1];
            float gn = GH[gi+2] + GH[1536 + gi+2] + GH[3072 + gi+2] + GH[4608 + gi+2];
            float z = sigf(gxs[b*24 + hl8]          + gz);
            float r = sigf(gxs[b*24 + 8 + hl8]      + gr);
            float n = tanhf_fast(gxs[b*24 + 16 + hl8] + r*gn);
            float mem = 0.f;
            #pragma unroll
            for (int kk = 0; kk < K_; kk++)
                mem = fmaf(wk[kk], hist[((t + kk) & 7)*512 + b*8 + hl8], mem);
            float hn = (1.0f - z)*n + z*mem;
            hist[(t & 7)*512 + b*8 + hl8] = hn;
            g_Hbuf[(size_t)(K_ + t)*BH + (size_t)b*H_ + hc] = hn;
            int mt = b >> 4, r16 = b & 15;
            int lane2 = (r16 & 7)*4 + a_tg;
            int j = (r16 >> 3) + 2*a_c4;
            imgn[((s*4 + mt)*32 + lane2)*4 + j] = to_tf32(hn);
        }

        // grid barrier
        __threadfence();
        __syncthreads();
        if (tid == 0) {
            atomicAdd(&g_bar, 1u);
            unsigned target = (unsigned)NCTA * (unsigned)(t + 1);
            while (*(volatile unsigned*)&g_bar < target) { __nanosleep(32); }
        }
        __syncthreads();
    }
}

// ---------------- tail ----------------
__global__ void tail_kernel(float* __restrict__ outTail)
{
    const int n = K_*BH;
    for (int i = blockIdx.x*blockDim.x + threadIdx.x; i < n; i += gridDim.x*blockDim.x)
        outTail[i] = g_Hbuf[(size_t)T_*BH + i];
}

// ---------------- launch ----------------
extern "C" void kernel_launch(void* const* d_in, const int* in_sizes, int n_in,
                              void* d_out, int out_size)
{
    const float* inputs = (const float*)d_in[0];
    const float* hidden = (const float*)d_in[1];
    const float* Wx     = (const float*)d_in[2];
    const float* Wh     = (const float*)d_in[3];
    const float* b      = (const float*)d_in[4];
    const float* Wo     = (const float*)d_in[5];
    const float* bo     = (const float*)d_in[6];
    const float* mp     = (const float*)d_in[7];
    float* out = (float*)d_out;

    void* gxp = nullptr; cudaGetSymbolAddress(&gxp, g_GX2);
    void* hbp = nullptr; cudaGetSymbolAddress(&hbp, g_Hbuf);
    void* wxi = nullptr; cudaGetSymbolAddress(&wxi, g_WxImg);
    void* woi = nullptr; cudaGetSymbolAddress(&woi, g_WoImg);

    cudaFuncSetAttribute(recur_mma, cudaFuncAttributeMaxDynamicSharedMemorySize, SMEM_REQ);

    init_kernel<<<256, 256>>>(hidden, mp);
    prep_wht<<<512, 256>>>(Wh);
    prep_wimg<<<512, 256>>>(Wx, (float*)wxi, G3, I_);
    prep_wimg<<<512, 256>>>(Wo, (float*)woi, O_, H_);

    // GX2 = X @ Wx + b  (slice-major layout, mode 1)
    mma_gemm<<<dim3(G3/128, (T_*B_)/128), 256>>>(inputs, (const float*)wxi, b,
                                                 (float*)gxp, T_*B_, G3, I_, 1);
    // recurrence
    recur_mma<<<NCTA, 256, SMEM_REQ>>>();
    // outs = H_all @ Wo + bo
    mma_gemm<<<dim3(O_/128, (T_*B_)/128), 256>>>((const float*)hbp + (size_t)K_*BH,
                                                 (const float*)woi, bo, out,
                                                 T_*B_, O_, H_, 0);
    if (out_size >= TBO + K_*BH)
        tail_kernel<<<256, 256>>>(out + TBO);
}

// round 10
// speedup vs baseline: 4.8404x; 1.1237x over previous
#include <cuda_runtime.h>
#include <cuda_fp16.h>
#include <cstdint>
#include <cstddef>

// ---------------- problem constants ----------------
#define T_   256
#define B_   64
#define I_   512
#define H_   1024
#define O_   512
#define K_   8
#define G3   3072
#define BH   65536
#define TBO  8388608

// ---------------- recurrence config ----------------
#define NCTA 128        // persistent CTAs; each owns 8 h-cols x 3 gates (N=24)
// smem byte offsets (dynamic)
#define SMO_BRES 0          // resident Wh fp16 B-image: 49152
#define SMO_ABUF 49152      // 3 x 16384 A chunk ring (fp16)
#define SMO_GH   49152      // GH alias on A ring (4x64x24 fp32 = 24576), post-loop only
#define SMO_GXS  98304      // gx slice stage: 6144
#define SMO_HIST 104448     // h history ring 8x64x8 fp32 = 16384
#define SMO_MB   120832     // full[3]@0, cons[3]@24, gx@48, bres@56
#define SMEM_REQ 120960

// ---------------- device scratch ----------------
__device__ float    g_GX2[(size_t)T_*NCTA*B_*24];  // gate preact, slice-major
__device__ float    g_Hbuf[(size_t)(K_+T_)*BH];    // hidden ring fp32
__device__ float    g_w[K_*H_];                    // GL weights, idx0 oldest
__device__ __half   g_AImg16[2][BH];               // h in A-fragment-major fp16, ping-pong (128KB ea)
__device__ __half   g_BImg16[(size_t)NCTA*24576];  // Wh B-fragment-major fp16 (6MB)
__device__ float    g_WxImg[(size_t)I_*G3];        // Wx fragment-major tf32 (6MB)
__device__ float    g_WoImg[(size_t)H_*O_];        // Wo fragment-major tf32 (2MB)
__device__ unsigned g_bar;

// ---------------- helpers ----------------
__device__ __forceinline__ uint32_t smem_u32(const void* p) {
    uint32_t a; asm("{ .reg .u64 t; cvta.to.shared.u64 t, %1; cvt.u32.u64 %0, t; }" : "=r"(a) : "l"(p));
    return a;
}
__device__ __forceinline__ void mbar_init(uint32_t m, uint32_t c) {
    asm volatile("mbarrier.init.shared.b64 [%0], %1;" :: "r"(m), "r"(c) : "memory");
}
__device__ __forceinline__ void mbar_arrive(uint32_t m) {
    asm volatile("mbarrier.arrive.shared.b64 _, [%0];" :: "r"(m) : "memory");
}
__device__ __forceinline__ void mbar_expect_tx(uint32_t m, uint32_t bytes) {
    asm volatile("mbarrier.arrive.expect_tx.shared.b64 _, [%0], %1;" :: "r"(m), "r"(bytes) : "memory");
}
__device__ __forceinline__ void mbar_wait(uint32_t m, uint32_t parity) {
    asm volatile(
        "{\n\t.reg .pred P;\n\t"
        "WL_%=:\n\t"
        "mbarrier.try_wait.parity.acquire.cta.shared::cta.b64 P, [%0], %1, 0x989680;\n\t"
        "@P bra WD_%=;\n\t"
        "bra WL_%=;\n\t"
        "WD_%=:\n\t}"
        :: "r"(m), "r"(parity) : "memory");
}
__device__ __forceinline__ void bulk_g2s(uint32_t dst, const void* src, uint32_t bytes, uint32_t mbar) {
    asm volatile("cp.async.bulk.shared::cluster.global.mbarrier::complete_tx::bytes [%0], [%1], %2, [%3];"
                 :: "r"(dst), "l"(src), "r"(bytes), "r"(mbar) : "memory");
}
__device__ __forceinline__ void cp16(uint32_t dst, const void* src) {
    asm volatile("cp.async.cg.shared.global [%0], [%1], 16;" :: "r"(dst), "l"(src));
}
__device__ __forceinline__ void cp_commit() { asm volatile("cp.async.commit_group;" ::: "memory"); }
__device__ __forceinline__ void cp_wait0() { asm volatile("cp.async.wait_group 0;" ::: "memory"); }
__device__ __forceinline__ void cp_wait1() { asm volatile("cp.async.wait_group 1;" ::: "memory"); }
__device__ __forceinline__ void mma_tf32(float* d, const uint32_t* a, const uint32_t* b) {
    asm("mma.sync.aligned.m16n8k8.row.col.f32.tf32.tf32.f32 "
        "{%0,%1,%2,%3},{%4,%5,%6,%7},{%8,%9},{%0,%1,%2,%3};"
        : "+f"(d[0]), "+f"(d[1]), "+f"(d[2]), "+f"(d[3])
        : "r"(a[0]), "r"(a[1]), "r"(a[2]), "r"(a[3]), "r"(b[0]), "r"(b[1]));
}
__device__ __forceinline__ void mma_fp16(float* d, const uint32_t* a, const uint32_t* b) {
    asm("mma.sync.aligned.m16n8k16.row.col.f32.f16.f16.f32 "
        "{%0,%1,%2,%3},{%4,%5,%6,%7},{%8,%9},{%0,%1,%2,%3};"
        : "+f"(d[0]), "+f"(d[1]), "+f"(d[2]), "+f"(d[3])
        : "r"(a[0]), "r"(a[1]), "r"(a[2]), "r"(a[3]), "r"(b[0]), "r"(b[1]));
}
__device__ __forceinline__ float to_tf32(float x) {
    float y; asm("cvt.rna.tf32.f32 %0, %1;" : "=f"(y) : "f"(x)); return y;
}
__device__ __forceinline__ float sigf(float x) { return 1.0f/(1.0f + __expf(-x)); }
__device__ __forceinline__ float tanhf_fast(float x) {
    float e = __expf(2.0f*x); return (e - 1.0f)/(e + 1.0f);
}

// fp16 A-fragment half-index for h[b][k]  (m16n8k16 .row A layout)
// regs r0={row g,k lo2}, r1={row g+8,k lo2}, r2={row g,k hi2}, r3={row g+8,k hi2}
__device__ __forceinline__ int aimg16_idx(int b, int k) {
    int ks16 = k >> 4, k16 = k & 15;
    int mt = b >> 4, r16 = b & 15;
    int g = r16 & 7, hi = r16 >> 3;
    int half = k16 >> 3, tq = (k16 & 7) >> 1, lo = k16 & 1;
    int lane = g*4 + tq;
    int r = hi + 2*half;
    return (((ks16*4 + mt)*32 + lane)*4 + r)*2 + lo;
}

// ---------------- init ----------------
__global__ void init_kernel(const float* __restrict__ hid, const float* __restrict__ mp)
{
    int idx = blockIdx.x*blockDim.x + threadIdx.x;
    int stride = gridDim.x*blockDim.x;
    if (idx == 0) g_bar = 0u;
    if (idx < H_) {
        float a = 0.5f / (1.0f + expf(-mp[idx]));
        float c = 1.0f;
        #pragma unroll
        for (int i = 0; i < K_; i++) {
            c *= ((float)i + a) / ((float)i + 1.0f);
            g_w[(K_-1-i)*H_ + idx] = c;
        }
    }
    for (int i = idx; i < K_*BH; i += stride) g_Hbuf[i] = hid[i];
    const float* h0 = hid + (size_t)(K_-1)*BH;
    for (int i = idx; i < BH; i += stride) {
        int b = i >> 10, k = i & 1023;
        g_AImg16[0][aimg16_idx(b, k)] = __float2half(h0[(size_t)b*H_ + k]);
    }
}

// ---------------- prep: Wh -> fp16 B-fragment image (slice = 8 h-cols, m16n8k16 .col B) ----------------
// regs r0={k16 2tq,2tq+1 col g}, r1={k16 8+2tq,9+2tq col g}
__global__ void prep_wht(const float* __restrict__ Wh)
{
    int idx = blockIdx.x*blockDim.x + threadIdx.x;
    int stride = gridDim.x*blockDim.x;
    const int total = H_*G3;
    for (int i = idx; i < total; i += stride) {
        int k = i / G3, col = i - k*G3;
        int gate = col >> 10, cw = col & 1023;
        int s = cw >> 3, hl8 = cw & 7;
        int nl = hl8*3 + gate;
        int nt = nl >> 3, g = nl & 7;
        int ks16 = k >> 4, k16 = k & 15;
        int r = k16 >> 3, tq = (k16 & 7) >> 1, lo = k16 & 1;
        int lane = g*4 + tq;
        size_t dst = ((((size_t)s*64 + ks16)*3 + nt)*32 + lane)*4 + r*2 + lo;
        g_BImg16[dst] = __float2half(Wh[i]);
    }
}

// ---------------- prep: generic weight -> tf32 GEMM B-fragment image ----------------
__global__ void prep_wimg(const float* __restrict__ W, float* __restrict__ img, int N, int K)
{
    int idx = blockIdx.x*blockDim.x + threadIdx.x;
    int stride = gridDim.x*blockDim.x;
    const int total = K*N, KC = K >> 4;
    for (int i = idx; i < total; i += stride) {
        int k = i / N, n = i - k*N;
        int nb = n >> 7, ntl = (n >> 3) & 15, g = n & 7;
        int kc = k >> 4, ks = (k >> 3) & 1, tq = k & 3, j = (k >> 2) & 1;
        int lane = g*4 + tq;
        size_t dst = ((((size_t)nb*KC + kc)*2 + ks)*16 + ntl)*32*2 + lane*2 + j;
        img[dst] = to_tf32(W[i]);
    }
}

// ---------------- tf32 HMMA GEMM: C = A @ W + bias (unchanged, validated) ----------------
__global__ __launch_bounds__(256) void mma_gemm(
    const float* __restrict__ A, const float* __restrict__ Wimg,
    const float* __restrict__ bias, float* __restrict__ C,
    int M, int N, int K, int mode)
{
    __shared__ float As[2][128][20];
    __shared__ float Bs[2][2048];
    const int tid = threadIdx.x;
    const int w = tid >> 5, l = tid & 31;
    const int wm = w >> 1, wn = w & 1;
    const int bn = blockIdx.x, bm = blockIdx.y;
    const int KC = K >> 4;
    const int g = l >> 2, tq = l & 3;

    float acc[2][8][4];
    #pragma unroll
    for (int mi = 0; mi < 2; mi++)
        #pragma unroll
        for (int ni = 0; ni < 8; ni++)
            #pragma unroll
            for (int q = 0; q < 4; q++) acc[mi][ni][q] = 0.0f;

    const float* Bsrc = Wimg + (size_t)bn*KC*2048;
    const int arow = tid >> 2, aseg = tid & 3;

    {
        #pragma unroll
        for (int r = 0; r < 2; r++) {
            int row = arow + r*64;
            cp16(smem_u32(&As[0][row][aseg*4]), A + (size_t)(bm*128 + row)*K + aseg*4);
            cp16(smem_u32(&Bs[0][(tid + r*256)*4]), Bsrc + (size_t)(tid + r*256)*4);
        }
        cp_commit();
    }

    int buf = 0;
    for (int kc = 0; kc < KC; kc++) {
        if (kc + 1 < KC) {
            #pragma unroll
            for (int r = 0; r < 2; r++) {
                int row = arow + r*64;
                cp16(smem_u32(&As[buf^1][row][aseg*4]),
                     A + (size_t)(bm*128 + row)*K + (kc+1)*16 + aseg*4);
                cp16(smem_u32(&Bs[buf^1][(tid + r*256)*4]),
                     Bsrc + (size_t)(kc+1)*2048 + (tid + r*256)*4);
            }
            cp_commit();
            cp_wait1();
        } else {
            cp_wait0();
        }
        __syncthreads();

        #pragma unroll
        for (int ks = 0; ks < 2; ks++) {
            uint32_t afr[2][4];
            #pragma unroll
            for (int mi = 0; mi < 2; mi++) {
                int r0 = wm*32 + mi*16 + g;
                afr[mi][0] = __float_as_uint(to_tf32(As[buf][r0    ][ks*8 + tq    ]));
                afr[mi][1] = __float_as_uint(to_tf32(As[buf][r0 + 8][ks*8 + tq    ]));
                afr[mi][2] = __float_as_uint(to_tf32(As[buf][r0    ][ks*8 + tq + 4]));
                afr[mi][3] = __float_as_uint(to_tf32(As[buf][r0 + 8][ks*8 + tq + 4]));
            }
            #pragma unroll
            for (int ni = 0; ni < 8; ni++) {
                float2 bv = *(const float2*)&Bs[buf][((ks*16 + wn*8 + ni)*32 + l)*2];
                uint32_t bfr[2] = { __float_as_uint(bv.x), __float_as_uint(bv.y) };
                #pragma unroll
                for (int mi = 0; mi < 2; mi++)
                    mma_tf32(acc[mi][ni], afr[mi], bfr);
            }
        }
        __syncthreads();
        buf ^= 1;
    }

    #pragma unroll
    for (int mi = 0; mi < 2; mi++) {
        int row0 = bm*128 + wm*32 + mi*16 + g;
        #pragma unroll
        for (int ni = 0; ni < 8; ni++) {
            int col = bn*128 + wn*64 + ni*8 + tq*2;
            float b0 = bias[col], b1 = bias[col+1];
            if (mode == 0) {
                *(float2*)&C[(size_t)row0*N + col] =
                    make_float2(acc[mi][ni][0] + b0, acc[mi][ni][1] + b1);
                *(float2*)&C[(size_t)(row0 + 8)*N + col] =
                    make_float2(acc[mi][ni][2] + b0, acc[mi][ni][3] + b1);
            } else {
                int gate = col >> 10, cw = col & 1023;
                int s2 = cw >> 3, hl = cw & 7;
                int tt = row0 >> 6, bb = row0 & 63;
                size_t base = ((size_t)tt*NCTA + s2)*64;
                *(float2*)&C[(base + bb)*24 + gate*8 + hl] =
                    make_float2(acc[mi][ni][0] + b0, acc[mi][ni][1] + b1);
                *(float2*)&C[(base + bb + 8)*24 + gate*8 + hl] =
                    make_float2(acc[mi][ni][2] + b0, acc[mi][ni][3] + b1);
            }
        }
    }
}

// ---------------- persistent fp16-HMMA recurrence v6 (R7 skeleton, fp16 operands) ----------------
extern __shared__ char smemRaw[];

__global__ __launch_bounds__(256, 1) void recur_mma()
{
    const int tid = threadIdx.x;
    const int w   = tid >> 5;
    const int l   = tid & 31;
    const int mw  = w & 1;           // M half: mt = 2*mw + mi
    const int ksp = w >> 1;          // K split 0..3
    const int s   = blockIdx.x;      // slice: h-cols s*8..s*8+7
    uint32_t smb  = smem_u32(smemRaw);
    uint32_t mbF0 = smb + SMO_MB;        // full[i] @ +8i
    uint32_t mbC0 = smb + SMO_MB + 24;   // cons[i] @ +8i
    uint32_t mbGX = smb + SMO_MB + 48;
    uint32_t mbBR = smb + SMO_MB + 56;
    const char* BresB = smemRaw + SMO_BRES;
    float* GH   = (float*)(smemRaw + SMO_GH);
    float* gxs  = (float*)(smemRaw + SMO_GXS);
    float* hist = (float*)(smemRaw + SMO_HIST);

    if (tid == 0) {
        #pragma unroll
        for (int i = 0; i < 3; i++) { mbar_init(mbF0 + 8*i, 1); mbar_init(mbC0 + 8*i, 8); }
        mbar_init(mbGX, 1); mbar_init(mbBR, 1);
    }
    __syncthreads();
    if (tid == 0) {
        mbar_expect_tx(mbBR, 49152);
        bulk_g2s(smb + SMO_BRES, (const char*)g_BImg16 + (size_t)s*49152, 49152, mbBR);
    }

    // hist ring init: hist[k][b][h8]
    for (int i = tid; i < K_*B_*8; i += 256) {
        int k = i >> 9, b = (i >> 3) & 63, h2 = i & 7;
        hist[i] = g_Hbuf[(size_t)k*BH + (size_t)b*H_ + s*8 + h2];
    }

    // epilogue constants
    const int hl8  = tid & 7;
    const int brow = tid >> 3;       // 0..31; b = brow, brow+32
    const int hc   = s*8 + hl8;
    float wk[K_];
    #pragma unroll
    for (int kk = 0; kk < K_; kk++) wk[kk] = g_w[kk*H_ + hc];
    // fp16 A-image write constants for k = hc
    const int a_ks16 = s >> 1;
    const int a_half = s & 1;              // reg offset 2*a_half
    const int a_tq   = hl8 >> 1;
    const int a_lo   = hl8 & 1;
    const int gg = l >> 2, tq = l & 3;

    mbar_wait(mbBR, 0);
    __syncthreads();

    for (int t = 0; t < T_; t++) {
        const char* aimg = (const char*)g_AImg16[t & 1];
        if (tid == 0) {
            mbar_expect_tx(mbGX, 6144);
            bulk_g2s(smb + SMO_GXS,
                     g_GX2 + (((size_t)t*NCTA + s)*64)*24, 6144, mbGX);
            #pragma unroll
            for (int cp = 0; cp < 3; cp++) {
                int gc = t*8 + cp, buf = gc % 3, f = gc / 3;
                if (f > 0) mbar_wait(mbC0 + 8*buf, (f - 1) & 1);
                mbar_expect_tx(mbF0 + 8*buf, 16384);
                bulk_g2s(smb + SMO_ABUF + buf*16384, aimg + (size_t)cp*16384, 16384, mbF0 + 8*buf);
            }
        }

        float acc[2][3][4];
        #pragma unroll
        for (int mi = 0; mi < 2; mi++)
            #pragma unroll
            for (int ni = 0; ni < 3; ni++)
                #pragma unroll
                for (int q = 0; q < 4; q++) acc[mi][ni][q] = 0.0f;

        #pragma unroll 1
        for (int c = 0; c < 8; c++) {
            const int gc = t*8 + c, buf = gc % 3, f = gc / 3;
            mbar_wait(mbF0 + 8*buf, f & 1);
            const char* Ab = smemRaw + SMO_ABUF + buf*16384;
            #pragma unroll
            for (int kl = 0; kl < 2; kl++) {
                const int ksl = ksp*2 + kl;          // local ks16 in chunk (0..7)
                const int ksg = c*8 + ksl;           // global ks16 (0..63)
                uint32_t afr[2][4];
                *(uint4*)afr[0] = *(const uint4*)(Ab + ((size_t)((ksl*4 + 2*mw    )*32 + l))*16);
                *(uint4*)afr[1] = *(const uint4*)(Ab + ((size_t)((ksl*4 + 2*mw + 1)*32 + l))*16);
                #pragma unroll
                for (int ni = 0; ni < 3; ni++) {
                    uint2 bv = *(const uint2*)(BresB + ((size_t)((ksg*3 + ni)*32 + l))*8);
                    uint32_t bfr[2] = { bv.x, bv.y };
                    #pragma unroll
                    for (int mi = 0; mi < 2; mi++)
                        mma_fp16(acc[mi][ni], afr[mi], bfr);
                }
            }
            __syncwarp();
            if (l == 0) mbar_arrive(mbC0 + 8*buf);
            if (tid == 0 && c < 5) {
                int gc2 = gc + 3, buf2 = gc2 % 3, f2 = gc2 / 3;
                mbar_wait(mbC0 + 8*buf2, (f2 - 1) & 1);
                mbar_expect_tx(mbF0 + 8*buf2, 16384);
                bulk_g2s(smb + SMO_ABUF + buf2*16384, aimg + (size_t)(c + 3)*16384, 16384, mbF0 + 8*buf2);
            }
        }
        __syncthreads();   // all buffer reads done -> GH alias safe

        // dump C fragments: GH[ksp][b][24]
        #pragma unroll
        for (int mi = 0; mi < 2; mi++) {
            int row0 = (2*mw + mi)*16 + gg;
            #pragma unroll
            for (int ni = 0; ni < 3; ni++) {
                int colb = ni*8 + tq*2;
                *(float2*)&GH[ksp*1536 + row0*24 + colb]       = make_float2(acc[mi][ni][0], acc[mi][ni][1]);
                *(float2*)&GH[ksp*1536 + (row0 + 8)*24 + colb] = make_float2(acc[mi][ni][2], acc[mi][ni][3]);
            }
        }
        __syncthreads();
        mbar_wait(mbGX, (uint32_t)(t & 1));

        // gates + fractional memory (2 (b,hl8) pairs per thread)
        __half* imgn = g_AImg16[(t + 1) & 1];
        #pragma unroll
        for (int i = 0; i < 2; i++) {
            int b = brow + i*32;
            int gi = b*24 + hl8*3;
            float gz = GH[gi] + GH[1536 + gi] + GH[3072 + gi] + GH[4608 + gi];
            float gr = GH[gi+1] + GH[1536 + gi+1] + GH[3072 + gi+1] + GH[4608 + gi+1];
            float gn = GH[gi+2] + GH[1536 + gi+2] + GH[3072 + gi+2] + GH[4608 + gi+2];
            float z = sigf(gxs[b*24 + hl8]          + gz);
            float r = sigf(gxs[b*24 + 8 + hl8]      + gr);
            float n = tanhf_fast(gxs[b*24 + 16 + hl8] + r*gn);
            float mem = 0.f;
            #pragma unroll
            for (int kk = 0; kk < K_; kk++)
                mem = fmaf(wk[kk], hist[((t + kk) & 7)*512 + b*8 + hl8], mem);
            float hn = (1.0f - z)*n + z*mem;
            hist[(t & 7)*512 + b*8 + hl8] = hn;
            g_Hbuf[(size_t)(K_ + t)*BH + (size_t)b*H_ + hc] = hn;
            // fp16 A-image write for next step
            int mt = b >> 4, r16 = b & 15;
            int g2 = r16 & 7, hi = r16 >> 3;
            int lane2 = g2*4 + a_tq;
            int rreg = hi + 2*a_half;
            imgn[(((a_ks16*4 + mt)*32 + lane2)*4 + rreg)*2 + a_lo] = __float2half(hn);
        }

        // grid barrier
        __threadfence();
        __syncthreads();
        if (tid == 0) {
            atomicAdd(&g_bar, 1u);
            unsigned target = (unsigned)NCTA * (unsigned)(t + 1);
            while (*(volatile unsigned*)&g_bar < target) { __nanosleep(32); }
        }
        __syncthreads();
    }
}

// ---------------- tail ----------------
__global__ void tail_kernel(float* __restrict__ outTail)
{
    const int n = K_*BH;
    for (int i = blockIdx.x*blockDim.x + threadIdx.x; i < n; i += gridDim.x*blockDim.x)
        outTail[i] = g_Hbuf[(size_t)T_*BH + i];
}

// ---------------- launch ----------------
extern "C" void kernel_launch(void* const* d_in, const int* in_sizes, int n_in,
                              void* d_out, int out_size)
{
    const float* inputs = (const float*)d_in[0];
    const float* hidden = (const float*)d_in[1];
    const float* Wx     = (const float*)d_in[2];
    const float* Wh     = (const float*)d_in[3];
    const float* b      = (const float*)d_in[4];
    const float* Wo     = (const float*)d_in[5];
    const float* bo     = (const float*)d_in[6];
    const float* mp     = (const float*)d_in[7];
    float* out = (float*)d_out;

    void* gxp = nullptr; cudaGetSymbolAddress(&gxp, g_GX2);
    void* hbp = nullptr; cudaGetSymbolAddress(&hbp, g_Hbuf);
    void* wxi = nullptr; cudaGetSymbolAddress(&wxi, g_WxImg);
    void* woi = nullptr; cudaGetSymbolAddress(&woi, g_WoImg);

    cudaFuncSetAttribute(recur_mma, cudaFuncAttributeMaxDynamicSharedMemorySize, SMEM_REQ);

    init_kernel<<<256, 256>>>(hidden, mp);
    prep_wht<<<512, 256>>>(Wh);
    prep_wimg<<<512, 256>>>(Wx, (float*)wxi, G3, I_);
    prep_wimg<<<512, 256>>>(Wo, (float*)woi, O_, H_);

    mma_gemm<<<dim3(G3/128, (T_*B_)/128), 256>>>(inputs, (const float*)wxi, b,
                                                 (float*)gxp, T_*B_, G3, I_, 1);
    recur_mma<<<NCTA, 256, SMEM_REQ>>>();
    mma_gemm<<<dim3(O_/128, (T_*B_)/128), 256>>>((const float*)hbp + (size_t)K_*BH,
                                                 (const float*)woi, bo, out,
                                                 T_*B_, O_, H_, 0);
    if (out_size >= TBO + K_*BH)
        tail_kernel<<<256, 256>>>(out + TBO);
}